// round 9
// baseline (speedup 1.0000x reference)
#include <cuda_runtime.h>
#include <math.h>

#define NN 50000
#define EE 800000
#define ETOT 850000
#define TT 50

// ---------------- scratch (static device globals; no allocations) ----------------
__device__ float d_h1[NN * 256];
__device__ float d_g1[NN * 256];
__device__ float d_h2[NN * 64];
__device__ float d_g2[NN * 64];
__device__ float d_as1[NN * 4];
__device__ float d_ad1[NN * 4];
__device__ float d_as2[NN];
__device__ float d_ad2[NN];
__device__ float d_lstm[NN * 32];
__device__ int   d_deg[NN + 1];
__device__ int   d_off[NN + 1];
__device__ int   d_cur[NN];
__device__ int   d_csr[ETOT];

// ---------------- small helpers ----------------
__device__ __forceinline__ float lrelu(float v) { return v > 0.f ? v : 0.2f * v; }
__device__ __forceinline__ float fsig(float x) { return __fdividef(1.f, 1.f + __expf(-x)); }
__device__ __forceinline__ float ftanh(float x) { return __fdividef(2.f, 1.f + __expf(-2.f * x)) - 1.f; }

__device__ __forceinline__ unsigned long long pk2(float a, float b) {
    unsigned long long r;
    asm("mov.b64 %0,{%1,%2};" : "=l"(r) : "f"(a), "f"(b));
    return r;
}
__device__ __forceinline__ unsigned long long fma2(unsigned long long a, unsigned long long b,
                                                   unsigned long long c) {
    unsigned long long d;
    asm("fma.rn.f32x2 %0,%1,%2,%3;" : "=l"(d) : "l"(a), "l"(b), "l"(c));
    return d;
}
__device__ __forceinline__ void upk2(unsigned long long v, float& a, float& b) {
    asm("mov.b64 {%0,%1},%2;" : "=f"(a), "=f"(b) : "l"(v));
}

// branchless online softmax update: (m, s) <- combine with value v (weight 1)
__device__ __forceinline__ void online_upd(float& m, float& s, float v) {
    float mn = fmaxf(m, v);
    s = s * __expf(m - mn) + __expf(v - mn);
    m = mn;
}
// combine two (m, s) partials
__device__ __forceinline__ void online_comb(float& m, float& s, float om, float os) {
    float mn = fmaxf(m, om);
    s = s * __expf(m - mn) + os * __expf(om - mn);
    m = mn;
}

// ---------------- CSR build ----------------
__global__ void k_zero_deg() {
    int i = blockIdx.x * blockDim.x + threadIdx.x;
    if (i <= NN) d_deg[i] = 0;
}

__global__ void k_hist(const int* __restrict__ ei) {
    int e = blockIdx.x * blockDim.x + threadIdx.x;
    if (e >= ETOT) return;
    int d = (e < EE) ? ei[EE + e] : (e - EE);
    atomicAdd(&d_deg[d], 1);
}

__global__ void k_scan() {
    __shared__ int sm[1024];
    __shared__ int carry;
    int tid = threadIdx.x;
    if (tid == 0) carry = 0;
    for (int base = 0; base < NN; base += 1024) {
        __syncthreads();
        int v = (base + tid < NN) ? d_deg[base + tid] : 0;
        sm[tid] = v;
        __syncthreads();
        for (int s = 1; s < 1024; s <<= 1) {
            int t = (tid >= s) ? sm[tid - s] : 0;
            __syncthreads();
            sm[tid] += t;
            __syncthreads();
        }
        int incl = sm[tid];
        int bc = carry;
        __syncthreads();
        if (base + tid < NN) {
            int ex = bc + incl - v;
            d_off[base + tid] = ex;
            d_cur[base + tid] = ex;
        }
        if (tid == 1023) carry = bc + incl;
    }
    __syncthreads();
    if (tid == 0) d_off[NN] = carry;
}

__global__ void k_scatter(const int* __restrict__ ei) {
    int e = blockIdx.x * blockDim.x + threadIdx.x;
    if (e >= ETOT) return;
    int s, d;
    if (e < EE) { s = ei[e]; d = ei[EE + e]; }
    else        { s = e - EE; d = s; }
    int p = atomicAdd(&d_cur[d], 1);
    d_csr[p] = s;
}

// ---------------- SGEMM 128x64 tile, f32x2 packed FMA, fused attention dots ----------------
template <int K, int MODE>
__global__ void __launch_bounds__(256) k_sgemm(const float* __restrict__ A,
                                               const float* __restrict__ B,
                                               float* __restrict__ C,
                                               int M, int N,
                                               const float* __restrict__ atts,
                                               const float* __restrict__ attd,
                                               float* __restrict__ oas,
                                               float* __restrict__ oad) {
    __shared__ float As[16][128];
    __shared__ float Bs[16][64];
    int tid = threadIdx.x;
    int tx = tid & 15, ty = tid >> 4;
    int row0 = blockIdx.y * 128, col0 = blockIdx.x * 64;
    int ar = tid >> 1;
    int ac = (tid & 1) * 8;
    int br = tid >> 4, bc = (tid & 15) * 4;
    bool aval = (row0 + ar) < M;
    const float* Ap = A + (size_t)(row0 + ar) * K + ac;
    unsigned long long acc[8][2];
#pragma unroll
    for (int i = 0; i < 8; i++) { acc[i][0] = 0ull; acc[i][1] = 0ull; }

#pragma unroll 1
    for (int k0 = 0; k0 < K; k0 += 16) {
        float4 a0 = make_float4(0.f, 0.f, 0.f, 0.f), a1 = a0;
        if (aval) {
            a0 = *(const float4*)(Ap + k0);
            a1 = *(const float4*)(Ap + k0 + 4);
        }
        As[ac + 0][ar] = a0.x; As[ac + 1][ar] = a0.y;
        As[ac + 2][ar] = a0.z; As[ac + 3][ar] = a0.w;
        As[ac + 4][ar] = a1.x; As[ac + 5][ar] = a1.y;
        As[ac + 6][ar] = a1.z; As[ac + 7][ar] = a1.w;
        *(float4*)&Bs[br][bc] = *(const float4*)(B + (size_t)(k0 + br) * N + col0 + bc);
        __syncthreads();
#pragma unroll
        for (int kk = 0; kk < 16; kk++) {
            float4 av0 = *(const float4*)&As[kk][ty * 8];
            float4 av1 = *(const float4*)&As[kk][ty * 8 + 4];
            ulonglong2 bp = *(const ulonglong2*)&Bs[kk][tx * 4];
            float av[8] = {av0.x, av0.y, av0.z, av0.w, av1.x, av1.y, av1.z, av1.w};
#pragma unroll
            for (int i = 0; i < 8; i++) {
                unsigned long long ai = pk2(av[i], av[i]);
                acc[i][0] = fma2(ai, bp.x, acc[i][0]);
                acc[i][1] = fma2(ai, bp.y, acc[i][1]);
            }
        }
        __syncthreads();
    }

    float4 sv, dv;
    if (MODE) {
        int h = (MODE == 1) ? blockIdx.x : 0;
        sv = *(const float4*)(atts + h * 64 + tx * 4);
        dv = *(const float4*)(attd + h * 64 + tx * 4);
    }
#pragma unroll
    for (int i = 0; i < 8; i++) {
        int r = row0 + ty * 8 + i;
        float o0, o1, o2, o3;
        upk2(acc[i][0], o0, o1);
        upk2(acc[i][1], o2, o3);
        if (r < M)
            *(float4*)(C + (size_t)r * N + col0 + tx * 4) = make_float4(o0, o1, o2, o3);
        if (MODE) {
            float ps = o0 * sv.x + o1 * sv.y + o2 * sv.z + o3 * sv.w;
            float pd = o0 * dv.x + o1 * dv.y + o2 * dv.z + o3 * dv.w;
#pragma unroll
            for (int s = 1; s < 16; s <<= 1) {
                ps += __shfl_xor_sync(0xffffffffu, ps, s);
                pd += __shfl_xor_sync(0xffffffffu, pd, s);
            }
            if (tx == 0 && r < M) {
                if (MODE == 1) {
                    oas[r * 4 + blockIdx.x] = ps;
                    oad[r * 4 + blockIdx.x] = pd;
                } else {
                    oas[r] = ps;
                    oad[r] = pd;
                }
            }
        }
    }
}

// ---------------- GAT layer 1: online softmax + batched-exp message gather ----------------
__global__ void __launch_bounds__(256) k_gat1(const float* __restrict__ bias) {
    int lane = threadIdx.x & 31, warp = threadIdx.x >> 5;
    int n = blockIdx.x * 8 + warp;
    if (n >= NN) return;
    int o0 = d_off[n], deg = d_off[n + 1] - o0;
    float4 ad4 = *(const float4*)(d_ad1 + (size_t)n * 4);

    // single online pass: per-head running (max, sum)
    float m0 = -1e30f, m1 = -1e30f, m2 = -1e30f, m3 = -1e30f;
    float e0 = 0.f, e1 = 0.f, e2 = 0.f, e3 = 0.f;
    for (int i = lane; i < deg; i += 32) {
        int s = d_csr[o0 + i];
        float4 a = __ldg((const float4*)(d_as1 + (size_t)s * 4));
        online_upd(m0, e0, lrelu(a.x + ad4.x));
        online_upd(m1, e1, lrelu(a.y + ad4.y));
        online_upd(m2, e2, lrelu(a.z + ad4.z));
        online_upd(m3, e3, lrelu(a.w + ad4.w));
    }
#pragma unroll
    for (int s = 16; s; s >>= 1) {
        online_comb(m0, e0, __shfl_xor_sync(0xffffffffu, m0, s), __shfl_xor_sync(0xffffffffu, e0, s));
        online_comb(m1, e1, __shfl_xor_sync(0xffffffffu, m1, s), __shfl_xor_sync(0xffffffffu, e1, s));
        online_comb(m2, e2, __shfl_xor_sync(0xffffffffu, m2, s), __shfl_xor_sync(0xffffffffu, e2, s));
        online_comb(m3, e3, __shfl_xor_sync(0xffffffffu, m3, s), __shfl_xor_sync(0xffffffffu, e3, s));
    }
    float i0 = __fdividef(1.f, e0 + 1e-16f);
    float i1 = __fdividef(1.f, e1 + 1e-16f);
    float i2 = __fdividef(1.f, e2 + 1e-16f);
    float i3 = __fdividef(1.f, e3 + 1e-16f);

    // lane covers channels [lane*8, lane*8+8) -> head h = lane>>3
    int h = lane >> 3;
    float ih = (h < 2) ? (h == 0 ? i0 : i1) : (h == 2 ? i2 : i3);

    // exp-producer role: lane computes w for edge sub = lane>>2, head hh = lane&3
    int sub = lane >> 2, hh = lane & 3;
    float adhh = (hh < 2) ? (hh == 0 ? ad4.x : ad4.y) : (hh == 2 ? ad4.z : ad4.w);
    float mhh  = (hh < 2) ? (hh == 0 ? m0 : m1) : (hh == 2 ? m2 : m3);

    // message accumulation: 8-edge batches, 4 exps per edge (one per head)
    float4 acc0 = make_float4(0.f, 0.f, 0.f, 0.f), acc1 = acc0;
    for (int j0 = 0; j0 < deg; j0 += 8) {
        int sld = (lane < 8 && j0 + lane < deg) ? d_csr[o0 + j0 + lane] : 0;
        int se = __shfl_sync(0xffffffffu, sld, sub);
        float a = __ldg(&d_as1[(size_t)se * 4 + hh]);
        float w_l = __expf(lrelu(a + adhh) - mhh);
        int lim = min(8, deg - j0);
        for (int j = 0; j < lim; j++) {
            int s = __shfl_sync(0xffffffffu, sld, j);
            float w = __shfl_sync(0xffffffffu, w_l, (j << 2) | h);
            const float4* hp = (const float4*)(d_h1 + (size_t)s * 256 + lane * 8);
            float4 v0 = __ldg(hp), v1 = __ldg(hp + 1);
            acc0.x = fmaf(w, v0.x, acc0.x); acc0.y = fmaf(w, v0.y, acc0.y);
            acc0.z = fmaf(w, v0.z, acc0.z); acc0.w = fmaf(w, v0.w, acc0.w);
            acc1.x = fmaf(w, v1.x, acc1.x); acc1.y = fmaf(w, v1.y, acc1.y);
            acc1.z = fmaf(w, v1.z, acc1.z); acc1.w = fmaf(w, v1.w, acc1.w);
        }
    }
    float4 b0 = *(const float4*)(bias + lane * 8);
    float4 b1 = *(const float4*)(bias + lane * 8 + 4);
    float o[8] = {acc0.x * ih + b0.x, acc0.y * ih + b0.y, acc0.z * ih + b0.z, acc0.w * ih + b0.w,
                  acc1.x * ih + b1.x, acc1.y * ih + b1.y, acc1.z * ih + b1.z, acc1.w * ih + b1.w};
#pragma unroll
    for (int i = 0; i < 8; i++) o[i] = o[i] > 0.f ? o[i] : expm1f(o[i]);
    float* gp = d_g1 + (size_t)n * 256 + lane * 8;
    *(float4*)gp       = make_float4(o[0], o[1], o[2], o[3]);
    *(float4*)(gp + 4) = make_float4(o[4], o[5], o[6], o[7]);
}

// ---------------- GAT layer 2: online softmax + batched-exp message gather ----------------
__global__ void __launch_bounds__(256) k_gat2(const float* __restrict__ bias) {
    int lane = threadIdx.x & 31, warp = threadIdx.x >> 5;
    int n = blockIdx.x * 8 + warp;
    if (n >= NN) return;
    int o0 = d_off[n], deg = d_off[n + 1] - o0;
    float ad = d_ad2[n];

    float m0 = -1e30f, e0 = 0.f;
    for (int i = lane; i < deg; i += 32) {
        int s = d_csr[o0 + i];
        online_upd(m0, e0, lrelu(__ldg(&d_as2[s]) + ad));
    }
#pragma unroll
    for (int s = 16; s; s >>= 1)
        online_comb(m0, e0, __shfl_xor_sync(0xffffffffu, m0, s), __shfl_xor_sync(0xffffffffu, e0, s));
    float inv = __fdividef(1.f, e0 + 1e-16f);

    // 32-edge batches: each lane computes the exp for its own edge, inner loop shfls
    float2 acc = make_float2(0.f, 0.f);
    for (int j0 = 0; j0 < deg; j0 += 32) {
        int sld = (j0 + lane < deg) ? d_csr[o0 + j0 + lane] : 0;
        float w_l = __expf(lrelu(__ldg(&d_as2[sld]) + ad) - m0);
        int lim = min(32, deg - j0);
        for (int j = 0; j < lim; j++) {
            int s = __shfl_sync(0xffffffffu, sld, j);
            float w = __shfl_sync(0xffffffffu, w_l, j);
            float2 v = __ldg((const float2*)(d_h2 + (size_t)s * 64 + lane * 2));
            acc.x = fmaf(w, v.x, acc.x);
            acc.y = fmaf(w, v.y, acc.y);
        }
    }
    float2 b = *(const float2*)(bias + lane * 2);
    *(float2*)(d_g2 + (size_t)n * 64 + lane * 2) =
        make_float2(acc.x * inv + b.x, acc.y * inv + b.y);
}

// ---------------- LSTM: 8 nodes/warp, W_hh in smem, unpacked-h broadcasts ----------------
__global__ void __launch_bounds__(128, 4) k_lstm(const float* __restrict__ seq,
                                                 const float* __restrict__ Wih,
                                                 const float* __restrict__ Whh,
                                                 const float* __restrict__ bih,
                                                 const float* __restrict__ bhh) {
    __shared__ ulonglong2 wt[32][32];               // [k][lane] = (whp_if, whp_go)  16KB
    __shared__ float hb[4][32][8];                  // [warp][k][node] raw floats    4KB
    __shared__ unsigned long long xb[4][3][8];      // [warp][feat][node] packed
    __shared__ float sq[32][152];                   // staged sequences              19KB

    int tid = threadIdx.x;
    int n0 = blockIdx.x * 32;

    for (int i = tid; i < 32 * 150; i += 128) {
        int node = i / 150, j = i - node * 150;
        int n = n0 + node;
        sq[node][j] = (n < NN) ? seq[(size_t)n * 150 + j] : 0.f;
    }

    for (int i = tid; i < 1024; i += 128) {
        int k = i >> 5, ln = i & 31;
        ulonglong2 w;
        w.x = pk2(__ldg(&Whh[ln * 32 + k]),        __ldg(&Whh[(ln + 32) * 32 + k]));
        w.y = pk2(__ldg(&Whh[(ln + 64) * 32 + k]), __ldg(&Whh[(ln + 96) * 32 + k]));
        wt[k][ln] = w;
    }

    int lane = tid & 31, warp = tid >> 5;

    unsigned long long wx_if[3], wx_go[3];
#pragma unroll
    for (int k = 0; k < 3; k++) {
        wx_if[k] = pk2(Wih[lane * 3 + k], Wih[(32 + lane) * 3 + k]);
        wx_go[k] = pk2(Wih[(64 + lane) * 3 + k], Wih[(96 + lane) * 3 + k]);
    }
    unsigned long long b_if = pk2(bih[lane] + bhh[lane], bih[32 + lane] + bhh[32 + lane]);
    unsigned long long b_go = pk2(bih[64 + lane] + bhh[64 + lane], bih[96 + lane] + bhh[96 + lane]);

    int nd3 = lane / 3, f3 = lane - nd3 * 3;
    bool xlane = (lane < 24);

    __syncthreads();

    float h[8], c[8];
#pragma unroll
    for (int j = 0; j < 8; j++) { h[j] = 0.f; c[j] = 0.f; }

#pragma unroll 1
    for (int t = 0; t < TT; t++) {
        if (xlane) {
            float xv = sq[warp * 8 + nd3][t * 3 + f3];
            xb[warp][f3][nd3] = pk2(xv, xv);
        }
        *(float4*)&hb[warp][lane][0] = make_float4(h[0], h[1], h[2], h[3]);
        *(float4*)&hb[warp][lane][4] = make_float4(h[4], h[5], h[6], h[7]);
        __syncwarp();

        unsigned long long zif[8], zgo[8];
#pragma unroll
        for (int j = 0; j < 8; j++) { zif[j] = b_if; zgo[j] = b_go; }
#pragma unroll
        for (int f = 0; f < 3; f++) {
            ulonglong2 xa = *(const ulonglong2*)&xb[warp][f][0];
            ulonglong2 xc = *(const ulonglong2*)&xb[warp][f][2];
            ulonglong2 xe = *(const ulonglong2*)&xb[warp][f][4];
            ulonglong2 xg = *(const ulonglong2*)&xb[warp][f][6];
            zif[0] = fma2(xa.x, wx_if[f], zif[0]); zgo[0] = fma2(xa.x, wx_go[f], zgo[0]);
            zif[1] = fma2(xa.y, wx_if[f], zif[1]); zgo[1] = fma2(xa.y, wx_go[f], zgo[1]);
            zif[2] = fma2(xc.x, wx_if[f], zif[2]); zgo[2] = fma2(xc.x, wx_go[f], zgo[2]);
            zif[3] = fma2(xc.y, wx_if[f], zif[3]); zgo[3] = fma2(xc.y, wx_go[f], zgo[3]);
            zif[4] = fma2(xe.x, wx_if[f], zif[4]); zgo[4] = fma2(xe.x, wx_go[f], zgo[4]);
            zif[5] = fma2(xe.y, wx_if[f], zif[5]); zgo[5] = fma2(xe.y, wx_go[f], zgo[5]);
            zif[6] = fma2(xg.x, wx_if[f], zif[6]); zgo[6] = fma2(xg.x, wx_go[f], zgo[6]);
            zif[7] = fma2(xg.y, wx_if[f], zif[7]); zgo[7] = fma2(xg.y, wx_go[f], zgo[7]);
        }
#pragma unroll
        for (int k = 0; k < 32; k++) {
            ulonglong2 w = wt[k][lane];
            float4 ha = *(const float4*)&hb[warp][k][0];
            float4 hc = *(const float4*)&hb[warp][k][4];
            unsigned long long p0 = pk2(ha.x, ha.x);
            unsigned long long p1 = pk2(ha.y, ha.y);
            zif[0] = fma2(p0, w.x, zif[0]); zgo[0] = fma2(p0, w.y, zgo[0]);
            zif[1] = fma2(p1, w.x, zif[1]); zgo[1] = fma2(p1, w.y, zgo[1]);
            unsigned long long p2 = pk2(ha.z, ha.z);
            unsigned long long p3 = pk2(ha.w, ha.w);
            zif[2] = fma2(p2, w.x, zif[2]); zgo[2] = fma2(p2, w.y, zgo[2]);
            zif[3] = fma2(p3, w.x, zif[3]); zgo[3] = fma2(p3, w.y, zgo[3]);
            unsigned long long p4 = pk2(hc.x, hc.x);
            unsigned long long p5 = pk2(hc.y, hc.y);
            zif[4] = fma2(p4, w.x, zif[4]); zgo[4] = fma2(p4, w.y, zgo[4]);
            zif[5] = fma2(p5, w.x, zif[5]); zgo[5] = fma2(p5, w.y, zgo[5]);
            unsigned long long p6 = pk2(hc.z, hc.z);
            unsigned long long p7 = pk2(hc.w, hc.w);
            zif[6] = fma2(p6, w.x, zif[6]); zgo[6] = fma2(p6, w.y, zgo[6]);
            zif[7] = fma2(p7, w.x, zif[7]); zgo[7] = fma2(p7, w.y, zgo[7]);
        }
        __syncwarp();
#pragma unroll
        for (int j = 0; j < 8; j++) {
            float zi, zf, zg, zo;
            upk2(zif[j], zi, zf);
            upk2(zgo[j], zg, zo);
            c[j] = fsig(zf) * c[j] + fsig(zi) * ftanh(zg);
            h[j] = fsig(zo) * ftanh(c[j]);
        }
    }
#pragma unroll
    for (int j = 0; j < 8; j++) {
        int n = n0 + warp * 8 + j;
        if (n < NN) d_lstm[(size_t)n * 32 + lane] = h[j];
    }
}

// ---------------- fusion MLP: one warp per node ----------------
__global__ void __launch_bounds__(128) k_fuse(const float* __restrict__ Wf1,
                                              const float* __restrict__ bf1,
                                              const float* __restrict__ Wf2,
                                              const float* __restrict__ bf2,
                                              float* __restrict__ out) {
    __shared__ float w1s[96 * 64];
    __shared__ float w2s[128];
    __shared__ float b1s[64];
    int tid = threadIdx.x;
    for (int i = tid; i < 6144; i += 128) w1s[i] = Wf1[i];
    w2s[tid] = Wf2[tid];
    if (tid < 64) b1s[tid] = bf1[tid];
    __syncthreads();
    int lane = tid & 31, warp = tid >> 5;
    int n = blockIdx.x * 4 + warp;
    if (n >= NN) return;
    float f0 = d_g2[(size_t)n * 64 + lane];
    float f1 = d_g2[(size_t)n * 64 + 32 + lane];
    float f2 = d_lstm[(size_t)n * 32 + lane];
    float a0 = b1s[lane], a1 = b1s[32 + lane];
#pragma unroll
    for (int k = 0; k < 96; k++) {
        float srcv = (k < 32) ? f0 : ((k < 64) ? f1 : f2);
        float fk = __shfl_sync(0xffffffffu, srcv, k & 31);
        a0 = fmaf(fk, w1s[k * 64 + lane], a0);
        a1 = fmaf(fk, w1s[k * 64 + 32 + lane], a1);
    }
    a0 = fmaxf(a0, 0.f);
    a1 = fmaxf(a1, 0.f);
    float o0 = a0 * w2s[lane * 2 + 0] + a1 * w2s[(32 + lane) * 2 + 0];
    float o1 = a0 * w2s[lane * 2 + 1] + a1 * w2s[(32 + lane) * 2 + 1];
#pragma unroll
    for (int s = 16; s; s >>= 1) {
        o0 += __shfl_xor_sync(0xffffffffu, o0, s);
        o1 += __shfl_xor_sync(0xffffffffu, o1, s);
    }
    if (lane == 0) {
        out[(size_t)n * 2 + 0] = o0 + bf2[0];
        out[(size_t)n * 2 + 1] = o1 + bf2[1];
    }
}

// ---------------- launch ----------------
extern "C" void kernel_launch(void* const* d_in, const int* in_sizes, int n_in,
                              void* d_out, int out_size) {
    const float* x    = (const float*)d_in[0];
    const int*   ei   = (const int*)d_in[1];
    const float* seq  = (const float*)d_in[2];
    const float* W1   = (const float*)d_in[3];
    const float* as1  = (const float*)d_in[4];
    const float* ad1  = (const float*)d_in[5];
    const float* b1   = (const float*)d_in[6];
    const float* W2   = (const float*)d_in[7];
    const float* as2  = (const float*)d_in[8];
    const float* ad2  = (const float*)d_in[9];
    const float* b2   = (const float*)d_in[10];
    const float* Wih  = (const float*)d_in[11];
    const float* Whh  = (const float*)d_in[12];
    const float* bih  = (const float*)d_in[13];
    const float* bhh  = (const float*)d_in[14];
    const float* Wf1  = (const float*)d_in[15];
    const float* bf1  = (const float*)d_in[16];
    const float* Wf2  = (const float*)d_in[17];
    const float* bf2  = (const float*)d_in[18];
    float* out = (float*)d_out;

    float *h1p, *g1p, *h2p, *as1p, *ad1p, *as2p, *ad2p;
    cudaGetSymbolAddress((void**)&h1p, d_h1);
    cudaGetSymbolAddress((void**)&g1p, d_g1);
    cudaGetSymbolAddress((void**)&h2p, d_h2);
    cudaGetSymbolAddress((void**)&as1p, d_as1);
    cudaGetSymbolAddress((void**)&ad1p, d_ad1);
    cudaGetSymbolAddress((void**)&as2p, d_as2);
    cudaGetSymbolAddress((void**)&ad2p, d_ad2);

    static cudaStream_t s_a = 0, s_c = 0;
    static cudaEvent_t e_fork = 0, e_a = 0, e_c = 0;
    if (!s_a) {
        cudaStreamCreateWithFlags(&s_a, cudaStreamNonBlocking);
        cudaStreamCreateWithFlags(&s_c, cudaStreamNonBlocking);
        cudaEventCreateWithFlags(&e_fork, cudaEventDisableTiming);
        cudaEventCreateWithFlags(&e_a, cudaEventDisableTiming);
        cudaEventCreateWithFlags(&e_c, cudaEventDisableTiming);
    }

    cudaEventRecord(e_fork, 0);
    cudaStreamWaitEvent(s_a, e_fork, 0);
    cudaStreamWaitEvent(s_c, e_fork, 0);

    // stream A: CSR build (lstm as 4th submitted kernel -> profiled slot)
    k_zero_deg<<<(NN + 256) / 256, 256, 0, s_a>>>();                  // 1
    k_hist<<<(ETOT + 255) / 256, 256, 0, s_a>>>(ei);                  // 2
    k_scan<<<1, 1024, 0, s_a>>>();                                    // 3
    k_lstm<<<(NN + 31) / 32, 128, 0, s_c>>>(seq, Wih, Whh, bih, bhh); // 4 (profiled slot)
    cudaEventRecord(e_c, s_c);
    k_scatter<<<(ETOT + 255) / 256, 256, 0, s_a>>>(ei);               // 5
    cudaEventRecord(e_a, s_a);

    // main stream: GAT chain (attention dots fused into GEMM epilogues)
    k_sgemm<128, 1><<<dim3(4, (NN + 127) / 128), 256>>>(x, W1, h1p, NN, 256,
                                                        as1, ad1, as1p, ad1p);
    cudaStreamWaitEvent(0, e_a, 0);
    k_gat1<<<(NN + 7) / 8, 256>>>(b1);
    k_sgemm<256, 2><<<dim3(1, (NN + 127) / 128), 256>>>(g1p, W2, h2p, NN, 64,
                                                        as2, ad2, as2p, ad2p);
    k_gat2<<<(NN + 7) / 8, 256>>>(b2);
    cudaStreamWaitEvent(0, e_c, 0);
    k_fuse<<<(NN + 3) / 4, 128>>>(Wf1, bf1, Wf2, bf2, out);
}

// round 10
// speedup vs baseline: 1.0152x; 1.0152x over previous
#include <cuda_runtime.h>
#include <math.h>

#define NN 50000
#define EE 800000
#define ETOT 850000
#define TT 50

// ---------------- scratch (static device globals; no allocations) ----------------
__device__ float d_h1[NN * 256];
__device__ float d_g1[NN * 256];
__device__ float d_h2[NN * 64];
__device__ float d_g2[NN * 64];
__device__ float d_as1[NN * 4];
__device__ float d_ad1[NN * 4];
__device__ float d_as2[NN];
__device__ float d_ad2[NN];
__device__ float d_lstm[NN * 32];
__device__ int   d_deg[NN + 1];
__device__ int   d_off[NN + 1];
__device__ int   d_cur[NN];
__device__ int   d_csr[ETOT];

// ---------------- small helpers ----------------
__device__ __forceinline__ float lrelu(float v) { return v > 0.f ? v : 0.2f * v; }
__device__ __forceinline__ float fsig(float x) { return __fdividef(1.f, 1.f + __expf(-x)); }
__device__ __forceinline__ float ftanh(float x) { return __fdividef(2.f, 1.f + __expf(-2.f * x)) - 1.f; }

__device__ __forceinline__ unsigned long long pk2(float a, float b) {
    unsigned long long r;
    asm("mov.b64 %0,{%1,%2};" : "=l"(r) : "f"(a), "f"(b));
    return r;
}
__device__ __forceinline__ unsigned long long fma2(unsigned long long a, unsigned long long b,
                                                   unsigned long long c) {
    unsigned long long d;
    asm("fma.rn.f32x2 %0,%1,%2,%3;" : "=l"(d) : "l"(a), "l"(b), "l"(c));
    return d;
}
__device__ __forceinline__ void upk2(unsigned long long v, float& a, float& b) {
    asm("mov.b64 {%0,%1},%2;" : "=f"(a), "=f"(b) : "l"(v));
}

__device__ __forceinline__ void online_upd(float& m, float& s, float v) {
    float mn = fmaxf(m, v);
    s = s * __expf(m - mn) + __expf(v - mn);
    m = mn;
}
__device__ __forceinline__ void online_comb(float& m, float& s, float om, float os) {
    float mn = fmaxf(m, om);
    s = s * __expf(m - mn) + os * __expf(om - mn);
    m = mn;
}

// ---------------- CSR build ----------------
__global__ void k_zero_deg() {
    int i = blockIdx.x * blockDim.x + threadIdx.x;
    if (i <= NN) d_deg[i] = 0;
}

__global__ void k_hist(const int* __restrict__ ei) {
    int e = blockIdx.x * blockDim.x + threadIdx.x;
    if (e >= ETOT) return;
    int d = (e < EE) ? ei[EE + e] : (e - EE);
    atomicAdd(&d_deg[d], 1);
}

__global__ void k_scan() {
    __shared__ int sm[1024];
    __shared__ int carry;
    int tid = threadIdx.x;
    if (tid == 0) carry = 0;
    for (int base = 0; base < NN; base += 1024) {
        __syncthreads();
        int v = (base + tid < NN) ? d_deg[base + tid] : 0;
        sm[tid] = v;
        __syncthreads();
        for (int s = 1; s < 1024; s <<= 1) {
            int t = (tid >= s) ? sm[tid - s] : 0;
            __syncthreads();
            sm[tid] += t;
            __syncthreads();
        }
        int incl = sm[tid];
        int bc = carry;
        __syncthreads();
        if (base + tid < NN) {
            int ex = bc + incl - v;
            d_off[base + tid] = ex;
            d_cur[base + tid] = ex;
        }
        if (tid == 1023) carry = bc + incl;
    }
    __syncthreads();
    if (tid == 0) d_off[NN] = carry;
}

__global__ void k_scatter(const int* __restrict__ ei) {
    int e = blockIdx.x * blockDim.x + threadIdx.x;
    if (e >= ETOT) return;
    int s, d;
    if (e < EE) { s = ei[e]; d = ei[EE + e]; }
    else        { s = e - EE; d = s; }
    int p = atomicAdd(&d_cur[d], 1);
    d_csr[p] = s;
}

// ---------------- SGEMM 128x64 tile, f32x2 packed FMA, fused attention dots ----------------
template <int K, int MODE>
__global__ void __launch_bounds__(256) k_sgemm(const float* __restrict__ A,
                                               const float* __restrict__ B,
                                               float* __restrict__ C,
                                               int M, int N,
                                               const float* __restrict__ atts,
                                               const float* __restrict__ attd,
                                               float* __restrict__ oas,
                                               float* __restrict__ oad) {
    __shared__ float As[16][128];
    __shared__ float Bs[16][64];
    int tid = threadIdx.x;
    int tx = tid & 15, ty = tid >> 4;
    int row0 = blockIdx.y * 128, col0 = blockIdx.x * 64;
    int ar = tid >> 1;
    int ac = (tid & 1) * 8;
    int br = tid >> 4, bc = (tid & 15) * 4;
    bool aval = (row0 + ar) < M;
    const float* Ap = A + (size_t)(row0 + ar) * K + ac;
    unsigned long long acc[8][2];
#pragma unroll
    for (int i = 0; i < 8; i++) { acc[i][0] = 0ull; acc[i][1] = 0ull; }

#pragma unroll 1
    for (int k0 = 0; k0 < K; k0 += 16) {
        float4 a0 = make_float4(0.f, 0.f, 0.f, 0.f), a1 = a0;
        if (aval) {
            a0 = *(const float4*)(Ap + k0);
            a1 = *(const float4*)(Ap + k0 + 4);
        }
        As[ac + 0][ar] = a0.x; As[ac + 1][ar] = a0.y;
        As[ac + 2][ar] = a0.z; As[ac + 3][ar] = a0.w;
        As[ac + 4][ar] = a1.x; As[ac + 5][ar] = a1.y;
        As[ac + 6][ar] = a1.z; As[ac + 7][ar] = a1.w;
        *(float4*)&Bs[br][bc] = *(const float4*)(B + (size_t)(k0 + br) * N + col0 + bc);
        __syncthreads();
#pragma unroll
        for (int kk = 0; kk < 16; kk++) {
            float4 av0 = *(const float4*)&As[kk][ty * 8];
            float4 av1 = *(const float4*)&As[kk][ty * 8 + 4];
            ulonglong2 bp = *(const ulonglong2*)&Bs[kk][tx * 4];
            float av[8] = {av0.x, av0.y, av0.z, av0.w, av1.x, av1.y, av1.z, av1.w};
#pragma unroll
            for (int i = 0; i < 8; i++) {
                unsigned long long ai = pk2(av[i], av[i]);
                acc[i][0] = fma2(ai, bp.x, acc[i][0]);
                acc[i][1] = fma2(ai, bp.y, acc[i][1]);
            }
        }
        __syncthreads();
    }

    float4 sv, dv;
    if (MODE) {
        int h = (MODE == 1) ? blockIdx.x : 0;
        sv = *(const float4*)(atts + h * 64 + tx * 4);
        dv = *(const float4*)(attd + h * 64 + tx * 4);
    }
#pragma unroll
    for (int i = 0; i < 8; i++) {
        int r = row0 + ty * 8 + i;
        float o0, o1, o2, o3;
        upk2(acc[i][0], o0, o1);
        upk2(acc[i][1], o2, o3);
        if (r < M)
            *(float4*)(C + (size_t)r * N + col0 + tx * 4) = make_float4(o0, o1, o2, o3);
        if (MODE) {
            float ps = o0 * sv.x + o1 * sv.y + o2 * sv.z + o3 * sv.w;
            float pd = o0 * dv.x + o1 * dv.y + o2 * dv.z + o3 * dv.w;
#pragma unroll
            for (int s = 1; s < 16; s <<= 1) {
                ps += __shfl_xor_sync(0xffffffffu, ps, s);
                pd += __shfl_xor_sync(0xffffffffu, pd, s);
            }
            if (tx == 0 && r < M) {
                if (MODE == 1) {
                    oas[r * 4 + blockIdx.x] = ps;
                    oad[r * 4 + blockIdx.x] = pd;
                } else {
                    oas[r] = ps;
                    oad[r] = pd;
                }
            }
        }
    }
}

// ---------------- GAT layer 1: online softmax + batched-exp message gather ----------------
__global__ void __launch_bounds__(256) k_gat1(const float* __restrict__ bias) {
    int lane = threadIdx.x & 31, warp = threadIdx.x >> 5;
    int n = blockIdx.x * 8 + warp;
    if (n >= NN) return;
    int o0 = d_off[n], deg = d_off[n + 1] - o0;
    float4 ad4 = *(const float4*)(d_ad1 + (size_t)n * 4);

    float m0 = -1e30f, m1 = -1e30f, m2 = -1e30f, m3 = -1e30f;
    float e0 = 0.f, e1 = 0.f, e2 = 0.f, e3 = 0.f;
    for (int i = lane; i < deg; i += 32) {
        int s = d_csr[o0 + i];
        float4 a = __ldg((const float4*)(d_as1 + (size_t)s * 4));
        online_upd(m0, e0, lrelu(a.x + ad4.x));
        online_upd(m1, e1, lrelu(a.y + ad4.y));
        online_upd(m2, e2, lrelu(a.z + ad4.z));
        online_upd(m3, e3, lrelu(a.w + ad4.w));
    }
#pragma unroll
    for (int s = 16; s; s >>= 1) {
        online_comb(m0, e0, __shfl_xor_sync(0xffffffffu, m0, s), __shfl_xor_sync(0xffffffffu, e0, s));
        online_comb(m1, e1, __shfl_xor_sync(0xffffffffu, m1, s), __shfl_xor_sync(0xffffffffu, e1, s));
        online_comb(m2, e2, __shfl_xor_sync(0xffffffffu, m2, s), __shfl_xor_sync(0xffffffffu, e2, s));
        online_comb(m3, e3, __shfl_xor_sync(0xffffffffu, m3, s), __shfl_xor_sync(0xffffffffu, e3, s));
    }
    float i0 = __fdividef(1.f, e0 + 1e-16f);
    float i1 = __fdividef(1.f, e1 + 1e-16f);
    float i2 = __fdividef(1.f, e2 + 1e-16f);
    float i3 = __fdividef(1.f, e3 + 1e-16f);

    int h = lane >> 3;
    float ih = (h < 2) ? (h == 0 ? i0 : i1) : (h == 2 ? i2 : i3);

    int sub = lane >> 2, hh = lane & 3;
    float adhh = (hh < 2) ? (hh == 0 ? ad4.x : ad4.y) : (hh == 2 ? ad4.z : ad4.w);
    float mhh  = (hh < 2) ? (hh == 0 ? m0 : m1) : (hh == 2 ? m2 : m3);

    float4 acc0 = make_float4(0.f, 0.f, 0.f, 0.f), acc1 = acc0;
    for (int j0 = 0; j0 < deg; j0 += 8) {
        int sld = (lane < 8 && j0 + lane < deg) ? d_csr[o0 + j0 + lane] : 0;
        int se = __shfl_sync(0xffffffffu, sld, sub);
        float a = __ldg(&d_as1[(size_t)se * 4 + hh]);
        float w_l = __expf(lrelu(a + adhh) - mhh);
        int lim = min(8, deg - j0);
        for (int j = 0; j < lim; j++) {
            int s = __shfl_sync(0xffffffffu, sld, j);
            float w = __shfl_sync(0xffffffffu, w_l, (j << 2) | h);
            const float4* hp = (const float4*)(d_h1 + (size_t)s * 256 + lane * 8);
            float4 v0 = __ldg(hp), v1 = __ldg(hp + 1);
            acc0.x = fmaf(w, v0.x, acc0.x); acc0.y = fmaf(w, v0.y, acc0.y);
            acc0.z = fmaf(w, v0.z, acc0.z); acc0.w = fmaf(w, v0.w, acc0.w);
            acc1.x = fmaf(w, v1.x, acc1.x); acc1.y = fmaf(w, v1.y, acc1.y);
            acc1.z = fmaf(w, v1.z, acc1.z); acc1.w = fmaf(w, v1.w, acc1.w);
        }
    }
    float4 b0 = *(const float4*)(bias + lane * 8);
    float4 b1 = *(const float4*)(bias + lane * 8 + 4);
    float o[8] = {acc0.x * ih + b0.x, acc0.y * ih + b0.y, acc0.z * ih + b0.z, acc0.w * ih + b0.w,
                  acc1.x * ih + b1.x, acc1.y * ih + b1.y, acc1.z * ih + b1.z, acc1.w * ih + b1.w};
#pragma unroll
    for (int i = 0; i < 8; i++) o[i] = o[i] > 0.f ? o[i] : expm1f(o[i]);
    float* gp = d_g1 + (size_t)n * 256 + lane * 8;
    *(float4*)gp       = make_float4(o[0], o[1], o[2], o[3]);
    *(float4*)(gp + 4) = make_float4(o[4], o[5], o[6], o[7]);
}

// ---------------- GAT layer 2: online softmax + batched-exp message gather ----------------
__global__ void __launch_bounds__(256) k_gat2(const float* __restrict__ bias) {
    int lane = threadIdx.x & 31, warp = threadIdx.x >> 5;
    int n = blockIdx.x * 8 + warp;
    if (n >= NN) return;
    int o0 = d_off[n], deg = d_off[n + 1] - o0;
    float ad = d_ad2[n];

    float m0 = -1e30f, e0 = 0.f;
    for (int i = lane; i < deg; i += 32) {
        int s = d_csr[o0 + i];
        online_upd(m0, e0, lrelu(__ldg(&d_as2[s]) + ad));
    }
#pragma unroll
    for (int s = 16; s; s >>= 1)
        online_comb(m0, e0, __shfl_xor_sync(0xffffffffu, m0, s), __shfl_xor_sync(0xffffffffu, e0, s));
    float inv = __fdividef(1.f, e0 + 1e-16f);

    float2 acc = make_float2(0.f, 0.f);
    for (int j0 = 0; j0 < deg; j0 += 32) {
        int sld = (j0 + lane < deg) ? d_csr[o0 + j0 + lane] : 0;
        float w_l = __expf(lrelu(__ldg(&d_as2[sld]) + ad) - m0);
        int lim = min(32, deg - j0);
        for (int j = 0; j < lim; j++) {
            int s = __shfl_sync(0xffffffffu, sld, j);
            float w = __shfl_sync(0xffffffffu, w_l, j);
            float2 v = __ldg((const float2*)(d_h2 + (size_t)s * 64 + lane * 2));
            acc.x = fmaf(w, v.x, acc.x);
            acc.y = fmaf(w, v.y, acc.y);
        }
    }
    float2 b = *(const float2*)(bias + lane * 2);
    *(float2*)(d_g2 + (size_t)n * 64 + lane * 2) =
        make_float2(acc.x * inv + b.x, acc.y * inv + b.y);
}

// ---------------- LSTM: 8 nodes/warp, W_hh in smem, unpacked-h broadcasts ----------------
__global__ void __launch_bounds__(128, 4) k_lstm(const float* __restrict__ seq,
                                                 const float* __restrict__ Wih,
                                                 const float* __restrict__ Whh,
                                                 const float* __restrict__ bih,
                                                 const float* __restrict__ bhh) {
    __shared__ ulonglong2 wt[32][32];
    __shared__ float hb[4][32][8];
    __shared__ unsigned long long xb[4][3][8];
    __shared__ float sq[32][152];

    int tid = threadIdx.x;
    int n0 = blockIdx.x * 32;

    for (int i = tid; i < 32 * 150; i += 128) {
        int node = i / 150, j = i - node * 150;
        int n = n0 + node;
        sq[node][j] = (n < NN) ? seq[(size_t)n * 150 + j] : 0.f;
    }

    for (int i = tid; i < 1024; i += 128) {
        int k = i >> 5, ln = i & 31;
        ulonglong2 w;
        w.x = pk2(__ldg(&Whh[ln * 32 + k]),        __ldg(&Whh[(ln + 32) * 32 + k]));
        w.y = pk2(__ldg(&Whh[(ln + 64) * 32 + k]), __ldg(&Whh[(ln + 96) * 32 + k]));
        wt[k][ln] = w;
    }

    int lane = tid & 31, warp = tid >> 5;

    unsigned long long wx_if[3], wx_go[3];
#pragma unroll
    for (int k = 0; k < 3; k++) {
        wx_if[k] = pk2(Wih[lane * 3 + k], Wih[(32 + lane) * 3 + k]);
        wx_go[k] = pk2(Wih[(64 + lane) * 3 + k], Wih[(96 + lane) * 3 + k]);
    }
    unsigned long long b_if = pk2(bih[lane] + bhh[lane], bih[32 + lane] + bhh[32 + lane]);
    unsigned long long b_go = pk2(bih[64 + lane] + bhh[64 + lane], bih[96 + lane] + bhh[96 + lane]);

    int nd3 = lane / 3, f3 = lane - nd3 * 3;
    bool xlane = (lane < 24);

    __syncthreads();

    float h[8], c[8];
#pragma unroll
    for (int j = 0; j < 8; j++) { h[j] = 0.f; c[j] = 0.f; }

#pragma unroll 1
    for (int t = 0; t < TT; t++) {
        if (xlane) {
            float xv = sq[warp * 8 + nd3][t * 3 + f3];
            xb[warp][f3][nd3] = pk2(xv, xv);
        }
        *(float4*)&hb[warp][lane][0] = make_float4(h[0], h[1], h[2], h[3]);
        *(float4*)&hb[warp][lane][4] = make_float4(h[4], h[5], h[6], h[7]);
        __syncwarp();

        unsigned long long zif[8], zgo[8];
#pragma unroll
        for (int j = 0; j < 8; j++) { zif[j] = b_if; zgo[j] = b_go; }
#pragma unroll
        for (int f = 0; f < 3; f++) {
            ulonglong2 xa = *(const ulonglong2*)&xb[warp][f][0];
            ulonglong2 xc = *(const ulonglong2*)&xb[warp][f][2];
            ulonglong2 xe = *(const ulonglong2*)&xb[warp][f][4];
            ulonglong2 xg = *(const ulonglong2*)&xb[warp][f][6];
            zif[0] = fma2(xa.x, wx_if[f], zif[0]); zgo[0] = fma2(xa.x, wx_go[f], zgo[0]);
            zif[1] = fma2(xa.y, wx_if[f], zif[1]); zgo[1] = fma2(xa.y, wx_go[f], zgo[1]);
            zif[2] = fma2(xc.x, wx_if[f], zif[2]); zgo[2] = fma2(xc.x, wx_go[f], zgo[2]);
            zif[3] = fma2(xc.y, wx_if[f], zif[3]); zgo[3] = fma2(xc.y, wx_go[f], zgo[3]);
            zif[4] = fma2(xe.x, wx_if[f], zif[4]); zgo[4] = fma2(xe.x, wx_go[f], zgo[4]);
            zif[5] = fma2(xe.y, wx_if[f], zif[5]); zgo[5] = fma2(xe.y, wx_go[f], zgo[5]);
            zif[6] = fma2(xg.x, wx_if[f], zif[6]); zgo[6] = fma2(xg.x, wx_go[f], zgo[6]);
            zif[7] = fma2(xg.y, wx_if[f], zif[7]); zgo[7] = fma2(xg.y, wx_go[f], zgo[7]);
        }
#pragma unroll
        for (int k = 0; k < 32; k++) {
            ulonglong2 w = wt[k][lane];
            float4 ha = *(const float4*)&hb[warp][k][0];
            float4 hc = *(const float4*)&hb[warp][k][4];
            unsigned long long p0 = pk2(ha.x, ha.x);
            unsigned long long p1 = pk2(ha.y, ha.y);
            zif[0] = fma2(p0, w.x, zif[0]); zgo[0] = fma2(p0, w.y, zgo[0]);
            zif[1] = fma2(p1, w.x, zif[1]); zgo[1] = fma2(p1, w.y, zgo[1]);
            unsigned long long p2 = pk2(ha.z, ha.z);
            unsigned long long p3 = pk2(ha.w, ha.w);
            zif[2] = fma2(p2, w.x, zif[2]); zgo[2] = fma2(p2, w.y, zgo[2]);
            zif[3] = fma2(p3, w.x, zif[3]); zgo[3] = fma2(p3, w.y, zgo[3]);
            unsigned long long p4 = pk2(hc.x, hc.x);
            unsigned long long p5 = pk2(hc.y, hc.y);
            zif[4] = fma2(p4, w.x, zif[4]); zgo[4] = fma2(p4, w.y, zgo[4]);
            zif[5] = fma2(p5, w.x, zif[5]); zgo[5] = fma2(p5, w.y, zgo[5]);
            unsigned long long p6 = pk2(hc.z, hc.z);
            unsigned long long p7 = pk2(hc.w, hc.w);
            zif[6] = fma2(p6, w.x, zif[6]); zgo[6] = fma2(p6, w.y, zgo[6]);
            zif[7] = fma2(p7, w.x, zif[7]); zgo[7] = fma2(p7, w.y, zgo[7]);
        }
        __syncwarp();
#pragma unroll
        for (int j = 0; j < 8; j++) {
            float zi, zf, zg, zo;
            upk2(zif[j], zi, zf);
            upk2(zgo[j], zg, zo);
            c[j] = fsig(zf) * c[j] + fsig(zi) * ftanh(zg);
            h[j] = fsig(zo) * ftanh(c[j]);
        }
    }
#pragma unroll
    for (int j = 0; j < 8; j++) {
        int n = n0 + warp * 8 + j;
        if (n < NN) d_lstm[(size_t)n * 32 + lane] = h[j];
    }
}

// ---------------- fusion MLP: one warp per node ----------------
__global__ void __launch_bounds__(128) k_fuse(const float* __restrict__ Wf1,
                                              const float* __restrict__ bf1,
                                              const float* __restrict__ Wf2,
                                              const float* __restrict__ bf2,
                                              float* __restrict__ out) {
    __shared__ float w1s[96 * 64];
    __shared__ float w2s[128];
    __shared__ float b1s[64];
    int tid = threadIdx.x;
    for (int i = tid; i < 6144; i += 128) w1s[i] = Wf1[i];
    w2s[tid] = Wf2[tid];
    if (tid < 64) b1s[tid] = bf1[tid];
    __syncthreads();
    int lane = tid & 31, warp = tid >> 5;
    int n = blockIdx.x * 4 + warp;
    if (n >= NN) return;
    float f0 = d_g2[(size_t)n * 64 + lane];
    float f1 = d_g2[(size_t)n * 64 + 32 + lane];
    float f2 = d_lstm[(size_t)n * 32 + lane];
    float a0 = b1s[lane], a1 = b1s[32 + lane];
#pragma unroll
    for (int k = 0; k < 96; k++) {
        float srcv = (k < 32) ? f0 : ((k < 64) ? f1 : f2);
        float fk = __shfl_sync(0xffffffffu, srcv, k & 31);
        a0 = fmaf(fk, w1s[k * 64 + lane], a0);
        a1 = fmaf(fk, w1s[k * 64 + 32 + lane], a1);
    }
    a0 = fmaxf(a0, 0.f);
    a1 = fmaxf(a1, 0.f);
    float o0 = a0 * w2s[lane * 2 + 0] + a1 * w2s[(32 + lane) * 2 + 0];
    float o1 = a0 * w2s[lane * 2 + 1] + a1 * w2s[(32 + lane) * 2 + 1];
#pragma unroll
    for (int s = 16; s; s >>= 1) {
        o0 += __shfl_xor_sync(0xffffffffu, o0, s);
        o1 += __shfl_xor_sync(0xffffffffu, o1, s);
    }
    if (lane == 0) {
        out[(size_t)n * 2 + 0] = o0 + bf2[0];
        out[(size_t)n * 2 + 1] = o1 + bf2[1];
    }
}

// ---------------- launch ----------------
extern "C" void kernel_launch(void* const* d_in, const int* in_sizes, int n_in,
                              void* d_out, int out_size) {
    const float* x    = (const float*)d_in[0];
    const int*   ei   = (const int*)d_in[1];
    const float* seq  = (const float*)d_in[2];
    const float* W1   = (const float*)d_in[3];
    const float* as1  = (const float*)d_in[4];
    const float* ad1  = (const float*)d_in[5];
    const float* b1   = (const float*)d_in[6];
    const float* W2   = (const float*)d_in[7];
    const float* as2  = (const float*)d_in[8];
    const float* ad2  = (const float*)d_in[9];
    const float* b2   = (const float*)d_in[10];
    const float* Wih  = (const float*)d_in[11];
    const float* Whh  = (const float*)d_in[12];
    const float* bih  = (const float*)d_in[13];
    const float* bhh  = (const float*)d_in[14];
    const float* Wf1  = (const float*)d_in[15];
    const float* bf1  = (const float*)d_in[16];
    const float* Wf2  = (const float*)d_in[17];
    const float* bf2  = (const float*)d_in[18];
    float* out = (float*)d_out;

    float *h1p, *g1p, *h2p, *as1p, *ad1p, *as2p, *ad2p;
    cudaGetSymbolAddress((void**)&h1p, d_h1);
    cudaGetSymbolAddress((void**)&g1p, d_g1);
    cudaGetSymbolAddress((void**)&h2p, d_h2);
    cudaGetSymbolAddress((void**)&as1p, d_as1);
    cudaGetSymbolAddress((void**)&ad1p, d_ad1);
    cudaGetSymbolAddress((void**)&as2p, d_as2);
    cudaGetSymbolAddress((void**)&ad2p, d_ad2);

    // one-time stream/event setup: LSTM on lowest priority, GAT stream highest.
    static cudaStream_t s_a = 0, s_c = 0, s_m = 0;
    static cudaEvent_t e_fork = 0, e_a = 0, e_c = 0, e_m = 0;
    if (!s_a) {
        int pLow, pHigh;
        cudaDeviceGetStreamPriorityRange(&pLow, &pHigh);
        cudaStreamCreateWithPriority(&s_a, cudaStreamNonBlocking, pHigh);
        cudaStreamCreateWithPriority(&s_m, cudaStreamNonBlocking, pHigh);
        cudaStreamCreateWithPriority(&s_c, cudaStreamNonBlocking, pLow);
        cudaEventCreateWithFlags(&e_fork, cudaEventDisableTiming);
        cudaEventCreateWithFlags(&e_a, cudaEventDisableTiming);
        cudaEventCreateWithFlags(&e_c, cudaEventDisableTiming);
        cudaEventCreateWithFlags(&e_m, cudaEventDisableTiming);
    }

    cudaEventRecord(e_fork, 0);
    cudaStreamWaitEvent(s_a, e_fork, 0);
    cudaStreamWaitEvent(s_c, e_fork, 0);
    cudaStreamWaitEvent(s_m, e_fork, 0);

    // high-priority GAT chain stream: GEMM1 enqueued BEFORE the LSTM flood
    k_sgemm<128, 1><<<dim3(4, (NN + 127) / 128), 256, 0, s_m>>>(x, W1, h1p, NN, 256,
                                                                as1, ad1, as1p, ad1p);

    // high-priority CSR build
    k_zero_deg<<<(NN + 256) / 256, 256, 0, s_a>>>();
    k_hist<<<(ETOT + 255) / 256, 256, 0, s_a>>>(ei);
    k_scan<<<1, 1024, 0, s_a>>>();
    k_scatter<<<(ETOT + 255) / 256, 256, 0, s_a>>>(ei);
    cudaEventRecord(e_a, s_a);

    // low-priority LSTM: fills whatever the GAT chain leaves idle
    k_lstm<<<(NN + 31) / 32, 128, 0, s_c>>>(seq, Wih, Whh, bih, bhh);
    cudaEventRecord(e_c, s_c);

    // rest of the GAT chain on the high-priority stream
    cudaStreamWaitEvent(s_m, e_a, 0);
    k_gat1<<<(NN + 7) / 8, 256, 0, s_m>>>(b1);
    k_sgemm<256, 2><<<dim3(1, (NN + 127) / 128), 256, 0, s_m>>>(g1p, W2, h2p, NN, 64,
                                                                as2, ad2, as2p, ad2p);
    k_gat2<<<(NN + 7) / 8, 256, 0, s_m>>>(b2);
    cudaStreamWaitEvent(s_m, e_c, 0);
    k_fuse<<<(NN + 3) / 4, 128, 0, s_m>>>(Wf1, bf1, Wf2, bf2, out);
    cudaEventRecord(e_m, s_m);
    cudaStreamWaitEvent(0, e_m, 0);
}

// round 11
// speedup vs baseline: 1.1042x; 1.0876x over previous
#include <cuda_runtime.h>
#include <math.h>

#define NN 50000
#define EE 800000
#define ETOT 850000
#define TT 50
#define NB ((NN + 1023) >> 10)

// ---------------- scratch (static device globals; no allocations) ----------------
__device__ float d_h1[NN * 256];
__device__ float d_g1[NN * 256];
__device__ float d_h2[NN * 64];
__device__ float d_g2[NN * 64];
__device__ float d_as1[NN * 4];
__device__ float d_ad1[NN * 4];
__device__ float d_as2[NN];
__device__ float d_ad2[NN];
__device__ float d_lstm[NN * 32];
__device__ int   d_deg[NN + 1];
__device__ int   d_off[NN + 1];
__device__ int   d_cur[NN];
__device__ int   d_csr[ETOT];
__device__ int   d_bsum[64];
__device__ int   d_boff[64];

// ---------------- small helpers ----------------
__device__ __forceinline__ float lrelu(float v) { return v > 0.f ? v : 0.2f * v; }
__device__ __forceinline__ float fsig(float x) { return __fdividef(1.f, 1.f + __expf(-x)); }
__device__ __forceinline__ float ftanh(float x) { return __fdividef(2.f, 1.f + __expf(-2.f * x)) - 1.f; }

__device__ __forceinline__ unsigned long long pk2(float a, float b) {
    unsigned long long r;
    asm("mov.b64 %0,{%1,%2};" : "=l"(r) : "f"(a), "f"(b));
    return r;
}
__device__ __forceinline__ unsigned long long fma2(unsigned long long a, unsigned long long b,
                                                   unsigned long long c) {
    unsigned long long d;
    asm("fma.rn.f32x2 %0,%1,%2,%3;" : "=l"(d) : "l"(a), "l"(b), "l"(c));
    return d;
}
__device__ __forceinline__ void upk2(unsigned long long v, float& a, float& b) {
    asm("mov.b64 {%0,%1},%2;" : "=f"(a), "=f"(b) : "l"(v));
}

__device__ __forceinline__ void online_upd(float& m, float& s, float v) {
    float mn = fmaxf(m, v);
    s = s * __expf(m - mn) + __expf(v - mn);
    m = mn;
}
__device__ __forceinline__ void online_comb(float& m, float& s, float om, float os) {
    float mn = fmaxf(m, om);
    s = s * __expf(m - mn) + os * __expf(om - mn);
    m = mn;
}

// ---------------- CSR build ----------------
__global__ void k_zero_deg() {
    int i = blockIdx.x * blockDim.x + threadIdx.x;
    if (i <= NN) d_deg[i] = 0;
}

__global__ void k_hist(const int* __restrict__ ei) {
    int e = blockIdx.x * blockDim.x + threadIdx.x;
    if (e >= ETOT) return;
    int d = (e < EE) ? ei[EE + e] : (e - EE);
    atomicAdd(&d_deg[d], 1);
}

// hierarchical scan: block-local inclusive -> block-sum scan -> apply
__global__ void k_scan1() {
    __shared__ int sm[1024];
    int b = blockIdx.x, tid = threadIdx.x;
    int idx = b * 1024 + tid;
    int v = (idx < NN) ? d_deg[idx] : 0;
    sm[tid] = v;
    __syncthreads();
    for (int s = 1; s < 1024; s <<= 1) {
        int t = (tid >= s) ? sm[tid - s] : 0;
        __syncthreads();
        sm[tid] += t;
        __syncthreads();
    }
    if (idx < NN) d_off[idx] = sm[tid];   // inclusive within block (temporary)
    if (tid == 1023) d_bsum[b] = sm[1023];
}

__global__ void k_scan2() {
    __shared__ int sm[64];
    int tid = threadIdx.x;
    int v = (tid < NB) ? d_bsum[tid] : 0;
    sm[tid] = v;
    __syncthreads();
    for (int s = 1; s < 64; s <<= 1) {
        int t = (tid >= s) ? sm[tid - s] : 0;
        __syncthreads();
        sm[tid] += t;
        __syncthreads();
    }
    d_boff[tid] = sm[tid] - v;            // exclusive block offset
    if (tid == NB - 1) d_off[NN] = sm[tid];
}

__global__ void k_scan3() {
    int i = blockIdx.x * blockDim.x + threadIdx.x;
    if (i >= NN) return;
    int ex = d_off[i] - d_deg[i] + d_boff[i >> 10];
    d_off[i] = ex;
    d_cur[i] = ex;
}

__global__ void k_scatter(const int* __restrict__ ei) {
    int e = blockIdx.x * blockDim.x + threadIdx.x;
    if (e >= ETOT) return;
    int s, d;
    if (e < EE) { s = ei[e]; d = ei[EE + e]; }
    else        { s = e - EE; d = s; }
    int p = atomicAdd(&d_cur[d], 1);
    d_csr[p] = s;
}

// ---------------- SGEMM 128x64 tile, f32x2 packed FMA, fused attention dots ----------------
template <int K, int MODE>
__global__ void __launch_bounds__(256) k_sgemm(const float* __restrict__ A,
                                               const float* __restrict__ B,
                                               float* __restrict__ C,
                                               int M, int N,
                                               const float* __restrict__ atts,
                                               const float* __restrict__ attd,
                                               float* __restrict__ oas,
                                               float* __restrict__ oad) {
    __shared__ float As[16][128];
    __shared__ float Bs[16][64];
    int tid = threadIdx.x;
    int tx = tid & 15, ty = tid >> 4;
    int row0 = blockIdx.y * 128, col0 = blockIdx.x * 64;
    int ar = tid >> 1;
    int ac = (tid & 1) * 8;
    int br = tid >> 4, bc = (tid & 15) * 4;
    bool aval = (row0 + ar) < M;
    const float* Ap = A + (size_t)(row0 + ar) * K + ac;
    unsigned long long acc[8][2];
#pragma unroll
    for (int i = 0; i < 8; i++) { acc[i][0] = 0ull; acc[i][1] = 0ull; }

#pragma unroll 1
    for (int k0 = 0; k0 < K; k0 += 16) {
        float4 a0 = make_float4(0.f, 0.f, 0.f, 0.f), a1 = a0;
        if (aval) {
            a0 = *(const float4*)(Ap + k0);
            a1 = *(const float4*)(Ap + k0 + 4);
        }
        As[ac + 0][ar] = a0.x; As[ac + 1][ar] = a0.y;
        As[ac + 2][ar] = a0.z; As[ac + 3][ar] = a0.w;
        As[ac + 4][ar] = a1.x; As[ac + 5][ar] = a1.y;
        As[ac + 6][ar] = a1.z; As[ac + 7][ar] = a1.w;
        *(float4*)&Bs[br][bc] = *(const float4*)(B + (size_t)(k0 + br) * N + col0 + bc);
        __syncthreads();
#pragma unroll
        for (int kk = 0; kk < 16; kk++) {
            float4 av0 = *(const float4*)&As[kk][ty * 8];
            float4 av1 = *(const float4*)&As[kk][ty * 8 + 4];
            ulonglong2 bp = *(const ulonglong2*)&Bs[kk][tx * 4];
            float av[8] = {av0.x, av0.y, av0.z, av0.w, av1.x, av1.y, av1.z, av1.w};
#pragma unroll
            for (int i = 0; i < 8; i++) {
                unsigned long long ai = pk2(av[i], av[i]);
                acc[i][0] = fma2(ai, bp.x, acc[i][0]);
                acc[i][1] = fma2(ai, bp.y, acc[i][1]);
            }
        }
        __syncthreads();
    }

    float4 sv, dv;
    if (MODE) {
        int h = (MODE == 1) ? blockIdx.x : 0;
        sv = *(const float4*)(atts + h * 64 + tx * 4);
        dv = *(const float4*)(attd + h * 64 + tx * 4);
    }
#pragma unroll
    for (int i = 0; i < 8; i++) {
        int r = row0 + ty * 8 + i;
        float o0, o1, o2, o3;
        upk2(acc[i][0], o0, o1);
        upk2(acc[i][1], o2, o3);
        if (r < M)
            *(float4*)(C + (size_t)r * N + col0 + tx * 4) = make_float4(o0, o1, o2, o3);
        if (MODE) {
            float ps = o0 * sv.x + o1 * sv.y + o2 * sv.z + o3 * sv.w;
            float pd = o0 * dv.x + o1 * dv.y + o2 * dv.z + o3 * dv.w;
#pragma unroll
            for (int s = 1; s < 16; s <<= 1) {
                ps += __shfl_xor_sync(0xffffffffu, ps, s);
                pd += __shfl_xor_sync(0xffffffffu, pd, s);
            }
            if (tx == 0 && r < M) {
                if (MODE == 1) {
                    oas[r * 4 + blockIdx.x] = ps;
                    oad[r * 4 + blockIdx.x] = pd;
                } else {
                    oas[r] = ps;
                    oad[r] = pd;
                }
            }
        }
    }
}

// ---------------- GAT layer 1: online softmax + batched-exp message gather ----------------
__global__ void __launch_bounds__(256) k_gat1(const float* __restrict__ bias) {
    int lane = threadIdx.x & 31, warp = threadIdx.x >> 5;
    int n = blockIdx.x * 8 + warp;
    if (n >= NN) return;
    int o0 = d_off[n], deg = d_off[n + 1] - o0;
    float4 ad4 = *(const float4*)(d_ad1 + (size_t)n * 4);

    float m0 = -1e30f, m1 = -1e30f, m2 = -1e30f, m3 = -1e30f;
    float e0 = 0.f, e1 = 0.f, e2 = 0.f, e3 = 0.f;
    for (int i = lane; i < deg; i += 32) {
        int s = d_csr[o0 + i];
        float4 a = __ldg((const float4*)(d_as1 + (size_t)s * 4));
        online_upd(m0, e0, lrelu(a.x + ad4.x));
        online_upd(m1, e1, lrelu(a.y + ad4.y));
        online_upd(m2, e2, lrelu(a.z + ad4.z));
        online_upd(m3, e3, lrelu(a.w + ad4.w));
    }
#pragma unroll
    for (int s = 16; s; s >>= 1) {
        online_comb(m0, e0, __shfl_xor_sync(0xffffffffu, m0, s), __shfl_xor_sync(0xffffffffu, e0, s));
        online_comb(m1, e1, __shfl_xor_sync(0xffffffffu, m1, s), __shfl_xor_sync(0xffffffffu, e1, s));
        online_comb(m2, e2, __shfl_xor_sync(0xffffffffu, m2, s), __shfl_xor_sync(0xffffffffu, e2, s));
        online_comb(m3, e3, __shfl_xor_sync(0xffffffffu, m3, s), __shfl_xor_sync(0xffffffffu, e3, s));
    }
    float i0 = __fdividef(1.f, e0 + 1e-16f);
    float i1 = __fdividef(1.f, e1 + 1e-16f);
    float i2 = __fdividef(1.f, e2 + 1e-16f);
    float i3 = __fdividef(1.f, e3 + 1e-16f);

    int h = lane >> 3;
    float ih = (h < 2) ? (h == 0 ? i0 : i1) : (h == 2 ? i2 : i3);

    int sub = lane >> 2, hh = lane & 3;
    float adhh = (hh < 2) ? (hh == 0 ? ad4.x : ad4.y) : (hh == 2 ? ad4.z : ad4.w);
    float mhh  = (hh < 2) ? (hh == 0 ? m0 : m1) : (hh == 2 ? m2 : m3);

    float4 acc0 = make_float4(0.f, 0.f, 0.f, 0.f), acc1 = acc0;
    for (int j0 = 0; j0 < deg; j0 += 8) {
        int sld = (lane < 8 && j0 + lane < deg) ? d_csr[o0 + j0 + lane] : 0;
        int se = __shfl_sync(0xffffffffu, sld, sub);
        float a = __ldg(&d_as1[(size_t)se * 4 + hh]);
        float w_l = __expf(lrelu(a + adhh) - mhh);
        int lim = min(8, deg - j0);
        for (int j = 0; j < lim; j++) {
            int s = __shfl_sync(0xffffffffu, sld, j);
            float w = __shfl_sync(0xffffffffu, w_l, (j << 2) | h);
            const float4* hp = (const float4*)(d_h1 + (size_t)s * 256 + lane * 8);
            float4 v0 = __ldg(hp), v1 = __ldg(hp + 1);
            acc0.x = fmaf(w, v0.x, acc0.x); acc0.y = fmaf(w, v0.y, acc0.y);
            acc0.z = fmaf(w, v0.z, acc0.z); acc0.w = fmaf(w, v0.w, acc0.w);
            acc1.x = fmaf(w, v1.x, acc1.x); acc1.y = fmaf(w, v1.y, acc1.y);
            acc1.z = fmaf(w, v1.z, acc1.z); acc1.w = fmaf(w, v1.w, acc1.w);
        }
    }
    float4 b0 = *(const float4*)(bias + lane * 8);
    float4 b1 = *(const float4*)(bias + lane * 8 + 4);
    float o[8] = {acc0.x * ih + b0.x, acc0.y * ih + b0.y, acc0.z * ih + b0.z, acc0.w * ih + b0.w,
                  acc1.x * ih + b1.x, acc1.y * ih + b1.y, acc1.z * ih + b1.z, acc1.w * ih + b1.w};
#pragma unroll
    for (int i = 0; i < 8; i++) o[i] = o[i] > 0.f ? o[i] : expm1f(o[i]);
    float* gp = d_g1 + (size_t)n * 256 + lane * 8;
    *(float4*)gp       = make_float4(o[0], o[1], o[2], o[3]);
    *(float4*)(gp + 4) = make_float4(o[4], o[5], o[6], o[7]);
}

// ---------------- GAT layer 2: online softmax + batched-exp message gather ----------------
__global__ void __launch_bounds__(256) k_gat2(const float* __restrict__ bias) {
    int lane = threadIdx.x & 31, warp = threadIdx.x >> 5;
    int n = blockIdx.x * 8 + warp;
    if (n >= NN) return;
    int o0 = d_off[n], deg = d_off[n + 1] - o0;
    float ad = d_ad2[n];

    float m0 = -1e30f, e0 = 0.f;
    for (int i = lane; i < deg; i += 32) {
        int s = d_csr[o0 + i];
        online_upd(m0, e0, lrelu(__ldg(&d_as2[s]) + ad));
    }
#pragma unroll
    for (int s = 16; s; s >>= 1)
        online_comb(m0, e0, __shfl_xor_sync(0xffffffffu, m0, s), __shfl_xor_sync(0xffffffffu, e0, s));
    float inv = __fdividef(1.f, e0 + 1e-16f);

    float2 acc = make_float2(0.f, 0.f);
    for (int j0 = 0; j0 < deg; j0 += 32) {
        int sld = (j0 + lane < deg) ? d_csr[o0 + j0 + lane] : 0;
        float w_l = __expf(lrelu(__ldg(&d_as2[sld]) + ad) - m0);
        int lim = min(32, deg - j0);
        for (int j = 0; j < lim; j++) {
            int s = __shfl_sync(0xffffffffu, sld, j);
            float w = __shfl_sync(0xffffffffu, w_l, j);
            float2 v = __ldg((const float2*)(d_h2 + (size_t)s * 64 + lane * 2));
            acc.x = fmaf(w, v.x, acc.x);
            acc.y = fmaf(w, v.y, acc.y);
        }
    }
    float2 b = *(const float2*)(bias + lane * 2);
    *(float2*)(d_g2 + (size_t)n * 64 + lane * 2) =
        make_float2(acc.x * inv + b.x, acc.y * inv + b.y);
}

// ---------------- LSTM: 8 nodes/warp, W_hh in smem, 5 blocks/SM ----------------
__global__ void __launch_bounds__(128, 5) k_lstm(const float* __restrict__ seq,
                                                 const float* __restrict__ Wih,
                                                 const float* __restrict__ Whh,
                                                 const float* __restrict__ bih,
                                                 const float* __restrict__ bhh) {
    __shared__ ulonglong2 wt[32][32];
    __shared__ float hb[4][32][8];
    __shared__ unsigned long long xb[4][3][8];
    __shared__ float sq[32][152];

    int tid = threadIdx.x;
    int n0 = blockIdx.x * 32;

    for (int i = tid; i < 32 * 150; i += 128) {
        int node = i / 150, j = i - node * 150;
        int n = n0 + node;
        sq[node][j] = (n < NN) ? seq[(size_t)n * 150 + j] : 0.f;
    }

    for (int i = tid; i < 1024; i += 128) {
        int k = i >> 5, ln = i & 31;
        ulonglong2 w;
        w.x = pk2(__ldg(&Whh[ln * 32 + k]),        __ldg(&Whh[(ln + 32) * 32 + k]));
        w.y = pk2(__ldg(&Whh[(ln + 64) * 32 + k]), __ldg(&Whh[(ln + 96) * 32 + k]));
        wt[k][ln] = w;
    }

    int lane = tid & 31, warp = tid >> 5;

    unsigned long long wx_if[3], wx_go[3];
#pragma unroll
    for (int k = 0; k < 3; k++) {
        wx_if[k] = pk2(Wih[lane * 3 + k], Wih[(32 + lane) * 3 + k]);
        wx_go[k] = pk2(Wih[(64 + lane) * 3 + k], Wih[(96 + lane) * 3 + k]);
    }
    unsigned long long b_if = pk2(bih[lane] + bhh[lane], bih[32 + lane] + bhh[32 + lane]);
    unsigned long long b_go = pk2(bih[64 + lane] + bhh[64 + lane], bih[96 + lane] + bhh[96 + lane]);

    int nd3 = lane / 3, f3 = lane - nd3 * 3;
    bool xlane = (lane < 24);

    __syncthreads();

    float h[8], c[8];
#pragma unroll
    for (int j = 0; j < 8; j++) { h[j] = 0.f; c[j] = 0.f; }

#pragma unroll 1
    for (int t = 0; t < TT; t++) {
        if (xlane) {
            float xv = sq[warp * 8 + nd3][t * 3 + f3];
            xb[warp][f3][nd3] = pk2(xv, xv);
        }
        *(float4*)&hb[warp][lane][0] = make_float4(h[0], h[1], h[2], h[3]);
        *(float4*)&hb[warp][lane][4] = make_float4(h[4], h[5], h[6], h[7]);
        __syncwarp();

        unsigned long long zif[8], zgo[8];
#pragma unroll
        for (int j = 0; j < 8; j++) { zif[j] = b_if; zgo[j] = b_go; }
#pragma unroll
        for (int f = 0; f < 3; f++) {
            ulonglong2 xa = *(const ulonglong2*)&xb[warp][f][0];
            ulonglong2 xc = *(const ulonglong2*)&xb[warp][f][2];
            ulonglong2 xe = *(const ulonglong2*)&xb[warp][f][4];
            ulonglong2 xg = *(const ulonglong2*)&xb[warp][f][6];
            zif[0] = fma2(xa.x, wx_if[f], zif[0]); zgo[0] = fma2(xa.x, wx_go[f], zgo[0]);
            zif[1] = fma2(xa.y, wx_if[f], zif[1]); zgo[1] = fma2(xa.y, wx_go[f], zgo[1]);
            zif[2] = fma2(xc.x, wx_if[f], zif[2]); zgo[2] = fma2(xc.x, wx_go[f], zgo[2]);
            zif[3] = fma2(xc.y, wx_if[f], zif[3]); zgo[3] = fma2(xc.y, wx_go[f], zgo[3]);
            zif[4] = fma2(xe.x, wx_if[f], zif[4]); zgo[4] = fma2(xe.x, wx_go[f], zgo[4]);
            zif[5] = fma2(xe.y, wx_if[f], zif[5]); zgo[5] = fma2(xe.y, wx_go[f], zgo[5]);
            zif[6] = fma2(xg.x, wx_if[f], zif[6]); zgo[6] = fma2(xg.x, wx_go[f], zgo[6]);
            zif[7] = fma2(xg.y, wx_if[f], zif[7]); zgo[7] = fma2(xg.y, wx_go[f], zgo[7]);
        }
#pragma unroll
        for (int k = 0; k < 32; k++) {
            ulonglong2 w = wt[k][lane];
            float4 ha = *(const float4*)&hb[warp][k][0];
            float4 hc = *(const float4*)&hb[warp][k][4];
            unsigned long long p0 = pk2(ha.x, ha.x);
            unsigned long long p1 = pk2(ha.y, ha.y);
            zif[0] = fma2(p0, w.x, zif[0]); zgo[0] = fma2(p0, w.y, zgo[0]);
            zif[1] = fma2(p1, w.x, zif[1]); zgo[1] = fma2(p1, w.y, zgo[1]);
            unsigned long long p2 = pk2(ha.z, ha.z);
            unsigned long long p3 = pk2(ha.w, ha.w);
            zif[2] = fma2(p2, w.x, zif[2]); zgo[2] = fma2(p2, w.y, zgo[2]);
            zif[3] = fma2(p3, w.x, zif[3]); zgo[3] = fma2(p3, w.y, zgo[3]);
            unsigned long long p4 = pk2(hc.x, hc.x);
            unsigned long long p5 = pk2(hc.y, hc.y);
            zif[4] = fma2(p4, w.x, zif[4]); zgo[4] = fma2(p4, w.y, zgo[4]);
            zif[5] = fma2(p5, w.x, zif[5]); zgo[5] = fma2(p5, w.y, zgo[5]);
            unsigned long long p6 = pk2(hc.z, hc.z);
            unsigned long long p7 = pk2(hc.w, hc.w);
            zif[6] = fma2(p6, w.x, zif[6]); zgo[6] = fma2(p6, w.y, zgo[6]);
            zif[7] = fma2(p7, w.x, zif[7]); zgo[7] = fma2(p7, w.y, zgo[7]);
        }
        __syncwarp();
#pragma unroll
        for (int j = 0; j < 8; j++) {
            float zi, zf, zg, zo;
            upk2(zif[j], zi, zf);
            upk2(zgo[j], zg, zo);
            c[j] = fsig(zf) * c[j] + fsig(zi) * ftanh(zg);
            h[j] = fsig(zo) * ftanh(c[j]);
        }
    }
#pragma unroll
    for (int j = 0; j < 8; j++) {
        int n = n0 + warp * 8 + j;
        if (n < NN) d_lstm[(size_t)n * 32 + lane] = h[j];
    }
}

// ---------------- fusion MLP: one warp per node ----------------
__global__ void __launch_bounds__(128) k_fuse(const float* __restrict__ Wf1,
                                              const float* __restrict__ bf1,
                                              const float* __restrict__ Wf2,
                                              const float* __restrict__ bf2,
                                              float* __restrict__ out) {
    __shared__ float w1s[96 * 64];
    __shared__ float w2s[128];
    __shared__ float b1s[64];
    int tid = threadIdx.x;
    for (int i = tid; i < 6144; i += 128) w1s[i] = Wf1[i];
    w2s[tid] = Wf2[tid];
    if (tid < 64) b1s[tid] = bf1[tid];
    __syncthreads();
    int lane = tid & 31, warp = tid >> 5;
    int n = blockIdx.x * 4 + warp;
    if (n >= NN) return;
    float f0 = d_g2[(size_t)n * 64 + lane];
    float f1 = d_g2[(size_t)n * 64 + 32 + lane];
    float f2 = d_lstm[(size_t)n * 32 + lane];
    float a0 = b1s[lane], a1 = b1s[32 + lane];
#pragma unroll
    for (int k = 0; k < 96; k++) {
        float srcv = (k < 32) ? f0 : ((k < 64) ? f1 : f2);
        float fk = __shfl_sync(0xffffffffu, srcv, k & 31);
        a0 = fmaf(fk, w1s[k * 64 + lane], a0);
        a1 = fmaf(fk, w1s[k * 64 + 32 + lane], a1);
    }
    a0 = fmaxf(a0, 0.f);
    a1 = fmaxf(a1, 0.f);
    float o0 = a0 * w2s[lane * 2 + 0] + a1 * w2s[(32 + lane) * 2 + 0];
    float o1 = a0 * w2s[lane * 2 + 1] + a1 * w2s[(32 + lane) * 2 + 1];
#pragma unroll
    for (int s = 16; s; s >>= 1) {
        o0 += __shfl_xor_sync(0xffffffffu, o0, s);
        o1 += __shfl_xor_sync(0xffffffffu, o1, s);
    }
    if (lane == 0) {
        out[(size_t)n * 2 + 0] = o0 + bf2[0];
        out[(size_t)n * 2 + 1] = o1 + bf2[1];
    }
}

// ---------------- launch ----------------
extern "C" void kernel_launch(void* const* d_in, const int* in_sizes, int n_in,
                              void* d_out, int out_size) {
    const float* x    = (const float*)d_in[0];
    const int*   ei   = (const int*)d_in[1];
    const float* seq  = (const float*)d_in[2];
    const float* W1   = (const float*)d_in[3];
    const float* as1  = (const float*)d_in[4];
    const float* ad1  = (const float*)d_in[5];
    const float* b1   = (const float*)d_in[6];
    const float* W2   = (const float*)d_in[7];
    const float* as2  = (const float*)d_in[8];
    const float* ad2  = (const float*)d_in[9];
    const float* b2   = (const float*)d_in[10];
    const float* Wih  = (const float*)d_in[11];
    const float* Whh  = (const float*)d_in[12];
    const float* bih  = (const float*)d_in[13];
    const float* bhh  = (const float*)d_in[14];
    const float* Wf1  = (const float*)d_in[15];
    const float* bf1  = (const float*)d_in[16];
    const float* Wf2  = (const float*)d_in[17];
    const float* bf2  = (const float*)d_in[18];
    float* out = (float*)d_out;

    float *h1p, *g1p, *h2p, *as1p, *ad1p, *as2p, *ad2p;
    cudaGetSymbolAddress((void**)&h1p, d_h1);
    cudaGetSymbolAddress((void**)&g1p, d_g1);
    cudaGetSymbolAddress((void**)&h2p, d_h2);
    cudaGetSymbolAddress((void**)&as1p, d_as1);
    cudaGetSymbolAddress((void**)&ad1p, d_ad1);
    cudaGetSymbolAddress((void**)&as2p, d_as2);
    cudaGetSymbolAddress((void**)&ad2p, d_ad2);

    static cudaStream_t s_a = 0, s_c = 0, s_m = 0;
    static cudaEvent_t e_fork = 0, e_a = 0, e_c = 0, e_m = 0;
    if (!s_a) {
        int pLow, pHigh;
        cudaDeviceGetStreamPriorityRange(&pLow, &pHigh);
        cudaStreamCreateWithPriority(&s_a, cudaStreamNonBlocking, pHigh);
        cudaStreamCreateWithPriority(&s_m, cudaStreamNonBlocking, pHigh);
        cudaStreamCreateWithPriority(&s_c, cudaStreamNonBlocking, pLow);
        cudaEventCreateWithFlags(&e_fork, cudaEventDisableTiming);
        cudaEventCreateWithFlags(&e_a, cudaEventDisableTiming);
        cudaEventCreateWithFlags(&e_c, cudaEventDisableTiming);
        cudaEventCreateWithFlags(&e_m, cudaEventDisableTiming);
    }

    cudaEventRecord(e_fork, 0);
    cudaStreamWaitEvent(s_a, e_fork, 0);
    cudaStreamWaitEvent(s_c, e_fork, 0);
    cudaStreamWaitEvent(s_m, e_fork, 0);

    // CSR build (fast hierarchical scan); sgemm1 enqueued 4th -> profiled slot
    k_zero_deg<<<(NN + 256) / 256, 256, 0, s_a>>>();                            // 1
    k_hist<<<(ETOT + 255) / 256, 256, 0, s_a>>>(ei);                            // 2
    k_scan1<<<NB, 1024, 0, s_a>>>();                                            // 3
    k_sgemm<128, 1><<<dim3(4, (NN + 127) / 128), 256, 0, s_m>>>(x, W1, h1p, NN, 256,
                                                                as1, ad1, as1p, ad1p); // 4
    k_scan2<<<1, 64, 0, s_a>>>();                                               // 5
    k_scan3<<<(NN + 255) / 256, 256, 0, s_a>>>();                               // 6
    k_scatter<<<(ETOT + 255) / 256, 256, 0, s_a>>>(ei);                         // 7
    cudaEventRecord(e_a, s_a);

    // low-priority LSTM
    k_lstm<<<(NN + 31) / 32, 128, 0, s_c>>>(seq, Wih, Whh, bih, bhh);
    cudaEventRecord(e_c, s_c);

    // rest of the GAT chain
    cudaStreamWaitEvent(s_m, e_a, 0);
    k_gat1<<<(NN + 7) / 8, 256, 0, s_m>>>(b1);
    k_sgemm<256, 2><<<dim3(1, (NN + 127) / 128), 256, 0, s_m>>>(g1p, W2, h2p, NN, 64,
                                                                as2, ad2, as2p, ad2p);
    k_gat2<<<(NN + 7) / 8, 256, 0, s_m>>>(b2);
    cudaStreamWaitEvent(s_m, e_c, 0);
    k_fuse<<<(NN + 3) / 4, 128, 0, s_m>>>(Wf1, bf1, Wf2, bf2, out);
    cudaEventRecord(e_m, s_m);
    cudaStreamWaitEvent(0, e_m, 0);
}

// round 12
// speedup vs baseline: 1.1169x; 1.0115x over previous
#include <cuda_runtime.h>
#include <math.h>

#define NN 50000
#define EE 800000
#define ETOT 850000
#define TT 50
#define NB ((NN + 1023) >> 10)

// ---------------- scratch (static device globals; no allocations) ----------------
__device__ float d_h1[NN * 256];
__device__ float d_g1[NN * 256];
__device__ float d_h2[NN * 64];
__device__ float d_g2[NN * 64];
__device__ float d_as1[NN * 4];
__device__ float d_ad1[NN * 4];
__device__ float d_as2[NN];
__device__ float d_ad2[NN];
__device__ float d_lstm[NN * 32];
__device__ int   d_deg[NN + 1];
__device__ int   d_off[NN + 1];
__device__ int   d_cur[NN];
__device__ int   d_csr[ETOT];
__device__ int   d_bsum[64];
__device__ int   d_boff[64];

// ---------------- small helpers ----------------
__device__ __forceinline__ float lrelu(float v) { return v > 0.f ? v : 0.2f * v; }
__device__ __forceinline__ float fsig(float x) { return __fdividef(1.f, 1.f + __expf(-x)); }
__device__ __forceinline__ float ftanh(float x) { return __fdividef(2.f, 1.f + __expf(-2.f * x)) - 1.f; }

__device__ __forceinline__ unsigned long long pk2(float a, float b) {
    unsigned long long r;
    asm("mov.b64 %0,{%1,%2};" : "=l"(r) : "f"(a), "f"(b));
    return r;
}
__device__ __forceinline__ unsigned long long fma2(unsigned long long a, unsigned long long b,
                                                   unsigned long long c) {
    unsigned long long d;
    asm("fma.rn.f32x2 %0,%1,%2,%3;" : "=l"(d) : "l"(a), "l"(b), "l"(c));
    return d;
}
__device__ __forceinline__ void upk2(unsigned long long v, float& a, float& b) {
    asm("mov.b64 {%0,%1},%2;" : "=f"(a), "=f"(b) : "l"(v));
}

__device__ __forceinline__ void online_upd(float& m, float& s, float v) {
    float mn = fmaxf(m, v);
    s = s * __expf(m - mn) + __expf(v - mn);
    m = mn;
}
__device__ __forceinline__ void online_comb(float& m, float& s, float om, float os) {
    float mn = fmaxf(m, om);
    s = s * __expf(m - mn) + os * __expf(om - mn);
    m = mn;
}

// ---------------- CSR build ----------------
__global__ void k_zero_deg() {
    int i = blockIdx.x * blockDim.x + threadIdx.x;
    if (i <= NN) d_deg[i] = 0;
}

__global__ void k_hist(const int* __restrict__ ei) {
    int e = blockIdx.x * blockDim.x + threadIdx.x;
    if (e >= ETOT) return;
    int d = (e < EE) ? ei[EE + e] : (e - EE);
    atomicAdd(&d_deg[d], 1);
}

__global__ void k_scan1() {
    __shared__ int sm[1024];
    int b = blockIdx.x, tid = threadIdx.x;
    int idx = b * 1024 + tid;
    int v = (idx < NN) ? d_deg[idx] : 0;
    sm[tid] = v;
    __syncthreads();
    for (int s = 1; s < 1024; s <<= 1) {
        int t = (tid >= s) ? sm[tid - s] : 0;
        __syncthreads();
        sm[tid] += t;
        __syncthreads();
    }
    if (idx < NN) d_off[idx] = sm[tid];
    if (tid == 1023) d_bsum[b] = sm[1023];
}

__global__ void k_scan2() {
    __shared__ int sm[64];
    int tid = threadIdx.x;
    int v = (tid < NB) ? d_bsum[tid] : 0;
    sm[tid] = v;
    __syncthreads();
    for (int s = 1; s < 64; s <<= 1) {
        int t = (tid >= s) ? sm[tid - s] : 0;
        __syncthreads();
        sm[tid] += t;
        __syncthreads();
    }
    d_boff[tid] = sm[tid] - v;
    if (tid == NB - 1) d_off[NN] = sm[tid];
}

__global__ void k_scan3() {
    int i = blockIdx.x * blockDim.x + threadIdx.x;
    if (i >= NN) return;
    int ex = d_off[i] - d_deg[i] + d_boff[i >> 10];
    d_off[i] = ex;
    d_cur[i] = ex;
}

__global__ void k_scatter(const int* __restrict__ ei) {
    int e = blockIdx.x * blockDim.x + threadIdx.x;
    if (e >= ETOT) return;
    int s, d;
    if (e < EE) { s = ei[e]; d = ei[EE + e]; }
    else        { s = e - EE; d = s; }
    int p = atomicAdd(&d_cur[d], 1);
    d_csr[p] = s;
}

// ---------------- SGEMM 128x64 tile, f32x2 packed FMA, fused attention dots ----------------
template <int K, int MODE>
__global__ void __launch_bounds__(256) k_sgemm(const float* __restrict__ A,
                                               const float* __restrict__ B,
                                               float* __restrict__ C,
                                               int M, int N,
                                               const float* __restrict__ atts,
                                               const float* __restrict__ attd,
                                               float* __restrict__ oas,
                                               float* __restrict__ oad) {
    __shared__ float As[16][128];
    __shared__ float Bs[16][64];
    int tid = threadIdx.x;
    int tx = tid & 15, ty = tid >> 4;
    int row0 = blockIdx.y * 128, col0 = blockIdx.x * 64;
    int ar = tid >> 1;
    int ac = (tid & 1) * 8;
    int br = tid >> 4, bc = (tid & 15) * 4;
    bool aval = (row0 + ar) < M;
    const float* Ap = A + (size_t)(row0 + ar) * K + ac;
    unsigned long long acc[8][2];
#pragma unroll
    for (int i = 0; i < 8; i++) { acc[i][0] = 0ull; acc[i][1] = 0ull; }

#pragma unroll 1
    for (int k0 = 0; k0 < K; k0 += 16) {
        float4 a0 = make_float4(0.f, 0.f, 0.f, 0.f), a1 = a0;
        if (aval) {
            a0 = *(const float4*)(Ap + k0);
            a1 = *(const float4*)(Ap + k0 + 4);
        }
        As[ac + 0][ar] = a0.x; As[ac + 1][ar] = a0.y;
        As[ac + 2][ar] = a0.z; As[ac + 3][ar] = a0.w;
        As[ac + 4][ar] = a1.x; As[ac + 5][ar] = a1.y;
        As[ac + 6][ar] = a1.z; As[ac + 7][ar] = a1.w;
        *(float4*)&Bs[br][bc] = *(const float4*)(B + (size_t)(k0 + br) * N + col0 + bc);
        __syncthreads();
#pragma unroll
        for (int kk = 0; kk < 16; kk++) {
            float4 av0 = *(const float4*)&As[kk][ty * 8];
            float4 av1 = *(const float4*)&As[kk][ty * 8 + 4];
            ulonglong2 bp = *(const ulonglong2*)&Bs[kk][tx * 4];
            float av[8] = {av0.x, av0.y, av0.z, av0.w, av1.x, av1.y, av1.z, av1.w};
#pragma unroll
            for (int i = 0; i < 8; i++) {
                unsigned long long ai = pk2(av[i], av[i]);
                acc[i][0] = fma2(ai, bp.x, acc[i][0]);
                acc[i][1] = fma2(ai, bp.y, acc[i][1]);
            }
        }
        __syncthreads();
    }

    float4 sv, dv;
    if (MODE) {
        int h = (MODE == 1) ? blockIdx.x : 0;
        sv = *(const float4*)(atts + h * 64 + tx * 4);
        dv = *(const float4*)(attd + h * 64 + tx * 4);
    }
#pragma unroll
    for (int i = 0; i < 8; i++) {
        int r = row0 + ty * 8 + i;
        float o0, o1, o2, o3;
        upk2(acc[i][0], o0, o1);
        upk2(acc[i][1], o2, o3);
        if (r < M)
            *(float4*)(C + (size_t)r * N + col0 + tx * 4) = make_float4(o0, o1, o2, o3);
        if (MODE) {
            float ps = o0 * sv.x + o1 * sv.y + o2 * sv.z + o3 * sv.w;
            float pd = o0 * dv.x + o1 * dv.y + o2 * dv.z + o3 * dv.w;
#pragma unroll
            for (int s = 1; s < 16; s <<= 1) {
                ps += __shfl_xor_sync(0xffffffffu, ps, s);
                pd += __shfl_xor_sync(0xffffffffu, pd, s);
            }
            if (tx == 0 && r < M) {
                if (MODE == 1) {
                    oas[r * 4 + blockIdx.x] = ps;
                    oad[r * 4 + blockIdx.x] = pd;
                } else {
                    oas[r] = ps;
                    oad[r] = pd;
                }
            }
        }
    }
}

// ---------------- GAT layer 1: online softmax + batched-exp message gather ----------------
__global__ void __launch_bounds__(256) k_gat1(const float* __restrict__ bias) {
    int lane = threadIdx.x & 31, warp = threadIdx.x >> 5;
    int n = blockIdx.x * 8 + warp;
    if (n >= NN) return;
    int o0 = d_off[n], deg = d_off[n + 1] - o0;
    float4 ad4 = *(const float4*)(d_ad1 + (size_t)n * 4);

    float m0 = -1e30f, m1 = -1e30f, m2 = -1e30f, m3 = -1e30f;
    float e0 = 0.f, e1 = 0.f, e2 = 0.f, e3 = 0.f;
    for (int i = lane; i < deg; i += 32) {
        int s = d_csr[o0 + i];
        float4 a = __ldg((const float4*)(d_as1 + (size_t)s * 4));
        online_upd(m0, e0, lrelu(a.x + ad4.x));
        online_upd(m1, e1, lrelu(a.y + ad4.y));
        online_upd(m2, e2, lrelu(a.z + ad4.z));
        online_upd(m3, e3, lrelu(a.w + ad4.w));
    }
#pragma unroll
    for (int s = 16; s; s >>= 1) {
        online_comb(m0, e0, __shfl_xor_sync(0xffffffffu, m0, s), __shfl_xor_sync(0xffffffffu, e0, s));
        online_comb(m1, e1, __shfl_xor_sync(0xffffffffu, m1, s), __shfl_xor_sync(0xffffffffu, e1, s));
        online_comb(m2, e2, __shfl_xor_sync(0xffffffffu, m2, s), __shfl_xor_sync(0xffffffffu, e2, s));
        online_comb(m3, e3, __shfl_xor_sync(0xffffffffu, m3, s), __shfl_xor_sync(0xffffffffu, e3, s));
    }
    float i0 = __fdividef(1.f, e0 + 1e-16f);
    float i1 = __fdividef(1.f, e1 + 1e-16f);
    float i2 = __fdividef(1.f, e2 + 1e-16f);
    float i3 = __fdividef(1.f, e3 + 1e-16f);

    int h = lane >> 3;
    float ih = (h < 2) ? (h == 0 ? i0 : i1) : (h == 2 ? i2 : i3);

    int sub = lane >> 2, hh = lane & 3;
    float adhh = (hh < 2) ? (hh == 0 ? ad4.x : ad4.y) : (hh == 2 ? ad4.z : ad4.w);
    float mhh  = (hh < 2) ? (hh == 0 ? m0 : m1) : (hh == 2 ? m2 : m3);

    float4 acc0 = make_float4(0.f, 0.f, 0.f, 0.f), acc1 = acc0;
    for (int j0 = 0; j0 < deg; j0 += 8) {
        int sld = (lane < 8 && j0 + lane < deg) ? d_csr[o0 + j0 + lane] : 0;
        int se = __shfl_sync(0xffffffffu, sld, sub);
        float a = __ldg(&d_as1[(size_t)se * 4 + hh]);
        float w_l = __expf(lrelu(a + adhh) - mhh);
        int lim = min(8, deg - j0);
        for (int j = 0; j < lim; j++) {
            int s = __shfl_sync(0xffffffffu, sld, j);
            float w = __shfl_sync(0xffffffffu, w_l, (j << 2) | h);
            const float4* hp = (const float4*)(d_h1 + (size_t)s * 256 + lane * 8);
            float4 v0 = __ldg(hp), v1 = __ldg(hp + 1);
            acc0.x = fmaf(w, v0.x, acc0.x); acc0.y = fmaf(w, v0.y, acc0.y);
            acc0.z = fmaf(w, v0.z, acc0.z); acc0.w = fmaf(w, v0.w, acc0.w);
            acc1.x = fmaf(w, v1.x, acc1.x); acc1.y = fmaf(w, v1.y, acc1.y);
            acc1.z = fmaf(w, v1.z, acc1.z); acc1.w = fmaf(w, v1.w, acc1.w);
        }
    }
    float4 b0 = *(const float4*)(bias + lane * 8);
    float4 b1 = *(const float4*)(bias + lane * 8 + 4);
    float o[8] = {acc0.x * ih + b0.x, acc0.y * ih + b0.y, acc0.z * ih + b0.z, acc0.w * ih + b0.w,
                  acc1.x * ih + b1.x, acc1.y * ih + b1.y, acc1.z * ih + b1.z, acc1.w * ih + b1.w};
#pragma unroll
    for (int i = 0; i < 8; i++) o[i] = o[i] > 0.f ? o[i] : expm1f(o[i]);
    float* gp = d_g1 + (size_t)n * 256 + lane * 8;
    *(float4*)gp       = make_float4(o[0], o[1], o[2], o[3]);
    *(float4*)(gp + 4) = make_float4(o[4], o[5], o[6], o[7]);
}

// ---------------- GAT layer 2: online softmax + batched-exp message gather ----------------
__global__ void __launch_bounds__(256) k_gat2(const float* __restrict__ bias) {
    int lane = threadIdx.x & 31, warp = threadIdx.x >> 5;
    int n = blockIdx.x * 8 + warp;
    if (n >= NN) return;
    int o0 = d_off[n], deg = d_off[n + 1] - o0;
    float ad = d_ad2[n];

    float m0 = -1e30f, e0 = 0.f;
    for (int i = lane; i < deg; i += 32) {
        int s = d_csr[o0 + i];
        online_upd(m0, e0, lrelu(__ldg(&d_as2[s]) + ad));
    }
#pragma unroll
    for (int s = 16; s; s >>= 1)
        online_comb(m0, e0, __shfl_xor_sync(0xffffffffu, m0, s), __shfl_xor_sync(0xffffffffu, e0, s));
    float inv = __fdividef(1.f, e0 + 1e-16f);

    float2 acc = make_float2(0.f, 0.f);
    for (int j0 = 0; j0 < deg; j0 += 32) {
        int sld = (j0 + lane < deg) ? d_csr[o0 + j0 + lane] : 0;
        float w_l = __expf(lrelu(__ldg(&d_as2[sld]) + ad) - m0);
        int lim = min(32, deg - j0);
        for (int j = 0; j < lim; j++) {
            int s = __shfl_sync(0xffffffffu, sld, j);
            float w = __shfl_sync(0xffffffffu, w_l, j);
            float2 v = __ldg((const float2*)(d_h2 + (size_t)s * 64 + lane * 2));
            acc.x = fmaf(w, v.x, acc.x);
            acc.y = fmaf(w, v.y, acc.y);
        }
    }
    float2 b = *(const float2*)(bias + lane * 2);
    *(float2*)(d_g2 + (size_t)n * 64 + lane * 2) =
        make_float2(acc.x * inv + b.x, acc.y * inv + b.y);
}

// ---------------- LSTM: node-pair f32x2 accumulators, W in smem, 5 blocks/SM ----------------
// Accumulator zz[gate][pair] = {z for node 2p, z for node 2p+1}: multiplier pairs
// {h_j, h_j+1} come straight from hb via ulonglong2 reinterpret (no pk2); only the
// weight {w,w} needs 4 pk2 per k. Same FP order as before -> bit-identical.
__global__ void __launch_bounds__(128, 5) k_lstm(const float* __restrict__ seq,
                                                 const float* __restrict__ Wih,
                                                 const float* __restrict__ Whh,
                                                 const float* __restrict__ bih,
                                                 const float* __restrict__ bhh) {
    __shared__ float4 wt[32][32];     // [k][lane] = {w_i, w_f, w_g, w_o}   16KB
    __shared__ float4 wxs[3][32];     // [feat][lane] = {wx_i, wx_f, wx_g, wx_o}
    __shared__ float hb[4][32][8];    // [warp][k][node] raw floats          4KB
    __shared__ float xb[4][3][8];     // [warp][feat][node] raw floats
    __shared__ float sq[32][152];     // staged sequences                   19KB

    int tid = threadIdx.x;
    int n0 = blockIdx.x * 32;

    for (int i = tid; i < 32 * 150; i += 128) {
        int node = i / 150, j = i - node * 150;
        int n = n0 + node;
        sq[node][j] = (n < NN) ? seq[(size_t)n * 150 + j] : 0.f;
    }

    for (int i = tid; i < 1024; i += 128) {
        int k = i >> 5, ln = i & 31;
        wt[k][ln] = make_float4(__ldg(&Whh[ln * 32 + k]),        __ldg(&Whh[(ln + 32) * 32 + k]),
                                __ldg(&Whh[(ln + 64) * 32 + k]), __ldg(&Whh[(ln + 96) * 32 + k]));
    }
    if (tid < 96) {
        int f = tid >> 5, ln = tid & 31;
        wxs[f][ln] = make_float4(Wih[ln * 3 + f],        Wih[(32 + ln) * 3 + f],
                                 Wih[(64 + ln) * 3 + f], Wih[(96 + ln) * 3 + f]);
    }

    int lane = tid & 31, warp = tid >> 5;

    unsigned long long b2[4];
#pragma unroll
    for (int g = 0; g < 4; g++) {
        float bv = bih[g * 32 + lane] + bhh[g * 32 + lane];
        b2[g] = pk2(bv, bv);
    }

    int nd3 = lane / 3, f3 = lane - nd3 * 3;
    bool xlane = (lane < 24);

    __syncthreads();

    float h[8], c[8];
#pragma unroll
    for (int j = 0; j < 8; j++) { h[j] = 0.f; c[j] = 0.f; }

#pragma unroll 1
    for (int t = 0; t < TT; t++) {
        if (xlane) xb[warp][f3][nd3] = sq[warp * 8 + nd3][t * 3 + f3];
        *(float4*)&hb[warp][lane][0] = make_float4(h[0], h[1], h[2], h[3]);
        *(float4*)&hb[warp][lane][4] = make_float4(h[4], h[5], h[6], h[7]);
        __syncwarp();

        unsigned long long zz[4][4];   // [gate i,f,g,o][node-pair]
#pragma unroll
        for (int g = 0; g < 4; g++)
#pragma unroll
            for (int p = 0; p < 4; p++) zz[g][p] = b2[g];

#pragma unroll
        for (int f = 0; f < 3; f++) {
            float4 wx = wxs[f][lane];
            unsigned long long wi2 = pk2(wx.x, wx.x);
            unsigned long long wf2 = pk2(wx.y, wx.y);
            unsigned long long wg2 = pk2(wx.z, wx.z);
            unsigned long long wo2 = pk2(wx.w, wx.w);
            ulonglong2 xA = *(const ulonglong2*)&xb[warp][f][0];
            ulonglong2 xB = *(const ulonglong2*)&xb[warp][f][4];
            zz[0][0] = fma2(xA.x, wi2, zz[0][0]); zz[0][1] = fma2(xA.y, wi2, zz[0][1]);
            zz[0][2] = fma2(xB.x, wi2, zz[0][2]); zz[0][3] = fma2(xB.y, wi2, zz[0][3]);
            zz[1][0] = fma2(xA.x, wf2, zz[1][0]); zz[1][1] = fma2(xA.y, wf2, zz[1][1]);
            zz[1][2] = fma2(xB.x, wf2, zz[1][2]); zz[1][3] = fma2(xB.y, wf2, zz[1][3]);
            zz[2][0] = fma2(xA.x, wg2, zz[2][0]); zz[2][1] = fma2(xA.y, wg2, zz[2][1]);
            zz[2][2] = fma2(xB.x, wg2, zz[2][2]); zz[2][3] = fma2(xB.y, wg2, zz[2][3]);
            zz[3][0] = fma2(xA.x, wo2, zz[3][0]); zz[3][1] = fma2(xA.y, wo2, zz[3][1]);
            zz[3][2] = fma2(xB.x, wo2, zz[3][2]); zz[3][3] = fma2(xB.y, wo2, zz[3][3]);
        }
#pragma unroll
        for (int k = 0; k < 32; k++) {
            float4 w4 = wt[k][lane];
            unsigned long long wi2 = pk2(w4.x, w4.x);
            unsigned long long wf2 = pk2(w4.y, w4.y);
            unsigned long long wg2 = pk2(w4.z, w4.z);
            unsigned long long wo2 = pk2(w4.w, w4.w);
            ulonglong2 hA = *(const ulonglong2*)&hb[warp][k][0];
            ulonglong2 hB = *(const ulonglong2*)&hb[warp][k][4];
            zz[0][0] = fma2(hA.x, wi2, zz[0][0]); zz[0][1] = fma2(hA.y, wi2, zz[0][1]);
            zz[0][2] = fma2(hB.x, wi2, zz[0][2]); zz[0][3] = fma2(hB.y, wi2, zz[0][3]);
            zz[1][0] = fma2(hA.x, wf2, zz[1][0]); zz[1][1] = fma2(hA.y, wf2, zz[1][1]);
            zz[1][2] = fma2(hB.x, wf2, zz[1][2]); zz[1][3] = fma2(hB.y, wf2, zz[1][3]);
            zz[2][0] = fma2(hA.x, wg2, zz[2][0]); zz[2][1] = fma2(hA.y, wg2, zz[2][1]);
            zz[2][2] = fma2(hB.x, wg2, zz[2][2]); zz[2][3] = fma2(hB.y, wg2, zz[2][3]);
            zz[3][0] = fma2(hA.x, wo2, zz[3][0]); zz[3][1] = fma2(hA.y, wo2, zz[3][1]);
            zz[3][2] = fma2(hB.x, wo2, zz[3][2]); zz[3][3] = fma2(hB.y, wo2, zz[3][3]);
        }
        __syncwarp();
#pragma unroll
        for (int p = 0; p < 4; p++) {
            float zi0, zi1, zf0, zf1, zg0, zg1, zo0, zo1;
            upk2(zz[0][p], zi0, zi1);
            upk2(zz[1][p], zf0, zf1);
            upk2(zz[2][p], zg0, zg1);
            upk2(zz[3][p], zo0, zo1);
            int j0 = 2 * p, j1 = 2 * p + 1;
            c[j0] = fsig(zf0) * c[j0] + fsig(zi0) * ftanh(zg0);
            h[j0] = fsig(zo0) * ftanh(c[j0]);
            c[j1] = fsig(zf1) * c[j1] + fsig(zi1) * ftanh(zg1);
            h[j1] = fsig(zo1) * ftanh(c[j1]);
        }
    }
#pragma unroll
    for (int j = 0; j < 8; j++) {
        int n = n0 + warp * 8 + j;
        if (n < NN) d_lstm[(size_t)n * 32 + lane] = h[j];
    }
}

// ---------------- fusion MLP: one warp per node ----------------
__global__ void __launch_bounds__(128) k_fuse(const float* __restrict__ Wf1,
                                              const float* __restrict__ bf1,
                                              const float* __restrict__ Wf2,
                                              const float* __restrict__ bf2,
                                              float* __restrict__ out) {
    __shared__ float w1s[96 * 64];
    __shared__ float w2s[128];
    __shared__ float b1s[64];
    int tid = threadIdx.x;
    for (int i = tid; i < 6144; i += 128) w1s[i] = Wf1[i];
    w2s[tid] = Wf2[tid];
    if (tid < 64) b1s[tid] = bf1[tid];
    __syncthreads();
    int lane = tid & 31, warp = tid >> 5;
    int n = blockIdx.x * 4 + warp;
    if (n >= NN) return;
    float f0 = d_g2[(size_t)n * 64 + lane];
    float f1 = d_g2[(size_t)n * 64 + 32 + lane];
    float f2 = d_lstm[(size_t)n * 32 + lane];
    float a0 = b1s[lane], a1 = b1s[32 + lane];
#pragma unroll
    for (int k = 0; k < 96; k++) {
        float srcv = (k < 32) ? f0 : ((k < 64) ? f1 : f2);
        float fk = __shfl_sync(0xffffffffu, srcv, k & 31);
        a0 = fmaf(fk, w1s[k * 64 + lane], a0);
        a1 = fmaf(fk, w1s[k * 64 + 32 + lane], a1);
    }
    a0 = fmaxf(a0, 0.f);
    a1 = fmaxf(a1, 0.f);
    float o0 = a0 * w2s[lane * 2 + 0] + a1 * w2s[(32 + lane) * 2 + 0];
    float o1 = a0 * w2s[lane * 2 + 1] + a1 * w2s[(32 + lane) * 2 + 1];
#pragma unroll
    for (int s = 16; s; s >>= 1) {
        o0 += __shfl_xor_sync(0xffffffffu, o0, s);
        o1 += __shfl_xor_sync(0xffffffffu, o1, s);
    }
    if (lane == 0) {
        out[(size_t)n * 2 + 0] = o0 + bf2[0];
        out[(size_t)n * 2 + 1] = o1 + bf2[1];
    }
}

// ---------------- launch ----------------
extern "C" void kernel_launch(void* const* d_in, const int* in_sizes, int n_in,
                              void* d_out, int out_size) {
    const float* x    = (const float*)d_in[0];
    const int*   ei   = (const int*)d_in[1];
    const float* seq  = (const float*)d_in[2];
    const float* W1   = (const float*)d_in[3];
    const float* as1  = (const float*)d_in[4];
    const float* ad1  = (const float*)d_in[5];
    const float* b1   = (const float*)d_in[6];
    const float* W2   = (const float*)d_in[7];
    const float* as2  = (const float*)d_in[8];
    const float* ad2  = (const float*)d_in[9];
    const float* b2   = (const float*)d_in[10];
    const float* Wih  = (const float*)d_in[11];
    const float* Whh  = (const float*)d_in[12];
    const float* bih  = (const float*)d_in[13];
    const float* bhh  = (const float*)d_in[14];
    const float* Wf1  = (const float*)d_in[15];
    const float* bf1  = (const float*)d_in[16];
    const float* Wf2  = (const float*)d_in[17];
    const float* bf2  = (const float*)d_in[18];
    float* out = (float*)d_out;

    float *h1p, *g1p, *h2p, *as1p, *ad1p, *as2p, *ad2p;
    cudaGetSymbolAddress((void**)&h1p, d_h1);
    cudaGetSymbolAddress((void**)&g1p, d_g1);
    cudaGetSymbolAddress((void**)&h2p, d_h2);
    cudaGetSymbolAddress((void**)&as1p, d_as1);
    cudaGetSymbolAddress((void**)&ad1p, d_ad1);
    cudaGetSymbolAddress((void**)&as2p, d_as2);
    cudaGetSymbolAddress((void**)&ad2p, d_ad2);

    static cudaStream_t s_a = 0, s_c = 0, s_m = 0;
    static cudaEvent_t e_fork = 0, e_a = 0, e_c = 0, e_m = 0;
    if (!s_a) {
        int pLow, pHigh;
        cudaDeviceGetStreamPriorityRange(&pLow, &pHigh);
        cudaStreamCreateWithPriority(&s_a, cudaStreamNonBlocking, pHigh);
        cudaStreamCreateWithPriority(&s_m, cudaStreamNonBlocking, pHigh);
        cudaStreamCreateWithPriority(&s_c, cudaStreamNonBlocking, pLow);
        cudaEventCreateWithFlags(&e_fork, cudaEventDisableTiming);
        cudaEventCreateWithFlags(&e_a, cudaEventDisableTiming);
        cudaEventCreateWithFlags(&e_c, cudaEventDisableTiming);
        cudaEventCreateWithFlags(&e_m, cudaEventDisableTiming);
    }

    cudaEventRecord(e_fork, 0);
    cudaStreamWaitEvent(s_a, e_fork, 0);
    cudaStreamWaitEvent(s_c, e_fork, 0);
    cudaStreamWaitEvent(s_m, e_fork, 0);

    // CSR build (hierarchical scan); sgemm1 enqueued 4th -> profiled slot (control)
    k_zero_deg<<<(NN + 256) / 256, 256, 0, s_a>>>();                            // 1
    k_hist<<<(ETOT + 255) / 256, 256, 0, s_a>>>(ei);                            // 2
    k_scan1<<<NB, 1024, 0, s_a>>>();                                            // 3
    k_sgemm<128, 1><<<dim3(4, (NN + 127) / 128), 256, 0, s_m>>>(x, W1, h1p, NN, 256,
                                                                as1, ad1, as1p, ad1p); // 4
    k_scan2<<<1, 64, 0, s_a>>>();                                               // 5
    k_scan3<<<(NN + 255) / 256, 256, 0, s_a>>>();                               // 6
    k_scatter<<<(ETOT + 255) / 256, 256, 0, s_a>>>(ei);                         // 7
    cudaEventRecord(e_a, s_a);

    // low-priority LSTM
    k_lstm<<<(NN + 31) / 32, 128, 0, s_c>>>(seq, Wih, Whh, bih, bhh);
    cudaEventRecord(e_c, s_c);

    // rest of the GAT chain
    cudaStreamWaitEvent(s_m, e_a, 0);
    k_gat1<<<(NN + 7) / 8, 256, 0, s_m>>>(b1);
    k_sgemm<256, 2><<<dim3(1, (NN + 127) / 128), 256, 0, s_m>>>(g1p, W2, h2p, NN, 64,
                                                                as2, ad2, as2p, ad2p);
    k_gat2<<<(NN + 7) / 8, 256, 0, s_m>>>(b2);
    cudaStreamWaitEvent(s_m, e_c, 0);
    k_fuse<<<(NN + 3) / 4, 128, 0, s_m>>>(Wf1, bf1, Wf2, bf2, out);
    cudaEventRecord(e_m, s_m);
    cudaStreamWaitEvent(0, e_m, 0);
}

// round 13
// speedup vs baseline: 1.1180x; 1.0010x over previous
#include <cuda_runtime.h>
#include <math.h>

#define NN 50000
#define EE 800000
#define ETOT 850000
#define TT 50
#define NB ((NN + 1023) >> 10)

// ---------------- scratch (static device globals; no allocations) ----------------
__device__ float d_h1[NN * 256];
__device__ float d_g1[NN * 256];
__device__ float d_h2[NN * 64];
__device__ float d_g2[NN * 64];
__device__ float d_as1[NN * 4];
__device__ float d_ad1[NN * 4];
__device__ float d_as2[NN];
__device__ float d_ad2[NN];
__device__ float d_lstm[NN * 32];
__device__ int   d_deg[NN + 1];
__device__ int   d_off[NN + 1];
__device__ int   d_cur[NN];
__device__ int   d_csr[ETOT];
__device__ int   d_bsum[64];
__device__ int   d_boff[64];

// ---------------- small helpers ----------------
__device__ __forceinline__ float lrelu(float v) { return v > 0.f ? v : 0.2f * v; }
__device__ __forceinline__ float fsig(float x) { return __fdividef(1.f, 1.f + __expf(-x)); }
__device__ __forceinline__ float ftanh(float x) { return __fdividef(2.f, 1.f + __expf(-2.f * x)) - 1.f; }

__device__ __forceinline__ unsigned long long pk2(float a, float b) {
    unsigned long long r;
    asm("mov.b64 %0,{%1,%2};" : "=l"(r) : "f"(a), "f"(b));
    return r;
}
__device__ __forceinline__ unsigned long long fma2(unsigned long long a, unsigned long long b,
                                                   unsigned long long c) {
    unsigned long long d;
    asm("fma.rn.f32x2 %0,%1,%2,%3;" : "=l"(d) : "l"(a), "l"(b), "l"(c));
    return d;
}
__device__ __forceinline__ void upk2(unsigned long long v, float& a, float& b) {
    asm("mov.b64 {%0,%1},%2;" : "=f"(a), "=f"(b) : "l"(v));
}

__device__ __forceinline__ void online_upd(float& m, float& s, float v) {
    float mn = fmaxf(m, v);
    s = s * __expf(m - mn) + __expf(v - mn);
    m = mn;
}
__device__ __forceinline__ void online_comb(float& m, float& s, float om, float os) {
    float mn = fmaxf(m, om);
    s = s * __expf(m - mn) + os * __expf(om - mn);
    m = mn;
}

// ---------------- CSR build ----------------
__global__ void k_zero_deg() {
    int i = blockIdx.x * blockDim.x + threadIdx.x;
    if (i <= NN) d_deg[i] = 0;
}

__global__ void k_hist(const int* __restrict__ ei) {
    int e = blockIdx.x * blockDim.x + threadIdx.x;
    if (e >= ETOT) return;
    int d = (e < EE) ? ei[EE + e] : (e - EE);
    atomicAdd(&d_deg[d], 1);
}

__global__ void k_scan1() {
    __shared__ int sm[1024];
    int b = blockIdx.x, tid = threadIdx.x;
    int idx = b * 1024 + tid;
    int v = (idx < NN) ? d_deg[idx] : 0;
    sm[tid] = v;
    __syncthreads();
    for (int s = 1; s < 1024; s <<= 1) {
        int t = (tid >= s) ? sm[tid - s] : 0;
        __syncthreads();
        sm[tid] += t;
        __syncthreads();
    }
    if (idx < NN) d_off[idx] = sm[tid];
    if (tid == 1023) d_bsum[b] = sm[1023];
}

__global__ void k_scan2() {
    __shared__ int sm[64];
    int tid = threadIdx.x;
    int v = (tid < NB) ? d_bsum[tid] : 0;
    sm[tid] = v;
    __syncthreads();
    for (int s = 1; s < 64; s <<= 1) {
        int t = (tid >= s) ? sm[tid - s] : 0;
        __syncthreads();
        sm[tid] += t;
        __syncthreads();
    }
    d_boff[tid] = sm[tid] - v;
    if (tid == NB - 1) d_off[NN] = sm[tid];
}

__global__ void k_scan3() {
    int i = blockIdx.x * blockDim.x + threadIdx.x;
    if (i >= NN) return;
    int ex = d_off[i] - d_deg[i] + d_boff[i >> 10];
    d_off[i] = ex;
    d_cur[i] = ex;
}

__global__ void k_scatter(const int* __restrict__ ei) {
    int e = blockIdx.x * blockDim.x + threadIdx.x;
    if (e >= ETOT) return;
    int s, d;
    if (e < EE) { s = ei[e]; d = ei[EE + e]; }
    else        { s = e - EE; d = s; }
    int p = atomicAdd(&d_cur[d], 1);
    d_csr[p] = s;
}

// ---------------- SGEMM 128x64 tile, f32x2 packed FMA, fused attention dots ----------------
template <int K, int MODE>
__global__ void __launch_bounds__(256) k_sgemm(const float* __restrict__ A,
                                               const float* __restrict__ B,
                                               float* __restrict__ C,
                                               int M, int N,
                                               const float* __restrict__ atts,
                                               const float* __restrict__ attd,
                                               float* __restrict__ oas,
                                               float* __restrict__ oad) {
    __shared__ float As[16][128];
    __shared__ float Bs[16][64];
    int tid = threadIdx.x;
    int tx = tid & 15, ty = tid >> 4;
    int row0 = blockIdx.y * 128, col0 = blockIdx.x * 64;
    int ar = tid >> 1;
    int ac = (tid & 1) * 8;
    int br = tid >> 4, bc = (tid & 15) * 4;
    bool aval = (row0 + ar) < M;
    const float* Ap = A + (size_t)(row0 + ar) * K + ac;
    unsigned long long acc[8][2];
#pragma unroll
    for (int i = 0; i < 8; i++) { acc[i][0] = 0ull; acc[i][1] = 0ull; }

#pragma unroll 1
    for (int k0 = 0; k0 < K; k0 += 16) {
        float4 a0 = make_float4(0.f, 0.f, 0.f, 0.f), a1 = a0;
        if (aval) {
            a0 = *(const float4*)(Ap + k0);
            a1 = *(const float4*)(Ap + k0 + 4);
        }
        As[ac + 0][ar] = a0.x; As[ac + 1][ar] = a0.y;
        As[ac + 2][ar] = a0.z; As[ac + 3][ar] = a0.w;
        As[ac + 4][ar] = a1.x; As[ac + 5][ar] = a1.y;
        As[ac + 6][ar] = a1.z; As[ac + 7][ar] = a1.w;
        *(float4*)&Bs[br][bc] = *(const float4*)(B + (size_t)(k0 + br) * N + col0 + bc);
        __syncthreads();
#pragma unroll
        for (int kk = 0; kk < 16; kk++) {
            float4 av0 = *(const float4*)&As[kk][ty * 8];
            float4 av1 = *(const float4*)&As[kk][ty * 8 + 4];
            ulonglong2 bp = *(const ulonglong2*)&Bs[kk][tx * 4];
            float av[8] = {av0.x, av0.y, av0.z, av0.w, av1.x, av1.y, av1.z, av1.w};
#pragma unroll
            for (int i = 0; i < 8; i++) {
                unsigned long long ai = pk2(av[i], av[i]);
                acc[i][0] = fma2(ai, bp.x, acc[i][0]);
                acc[i][1] = fma2(ai, bp.y, acc[i][1]);
            }
        }
        __syncthreads();
    }

    float4 sv, dv;
    if (MODE) {
        int h = (MODE == 1) ? blockIdx.x : 0;
        sv = *(const float4*)(atts + h * 64 + tx * 4);
        dv = *(const float4*)(attd + h * 64 + tx * 4);
    }
#pragma unroll
    for (int i = 0; i < 8; i++) {
        int r = row0 + ty * 8 + i;
        float o0, o1, o2, o3;
        upk2(acc[i][0], o0, o1);
        upk2(acc[i][1], o2, o3);
        if (r < M)
            *(float4*)(C + (size_t)r * N + col0 + tx * 4) = make_float4(o0, o1, o2, o3);
        if (MODE) {
            float ps = o0 * sv.x + o1 * sv.y + o2 * sv.z + o3 * sv.w;
            float pd = o0 * dv.x + o1 * dv.y + o2 * dv.z + o3 * dv.w;
#pragma unroll
            for (int s = 1; s < 16; s <<= 1) {
                ps += __shfl_xor_sync(0xffffffffu, ps, s);
                pd += __shfl_xor_sync(0xffffffffu, pd, s);
            }
            if (tx == 0 && r < M) {
                if (MODE == 1) {
                    oas[r * 4 + blockIdx.x] = ps;
                    oad[r * 4 + blockIdx.x] = pd;
                } else {
                    oas[r] = ps;
                    oad[r] = pd;
                }
            }
        }
    }
}

// ---------------- GAT layer 1: 128-thread blocks (co-residable with LSTM) ----------------
__global__ void __launch_bounds__(128, 5) k_gat1(const float* __restrict__ bias) {
    int lane = threadIdx.x & 31, warp = threadIdx.x >> 5;
    int n = blockIdx.x * 4 + warp;
    if (n >= NN) return;
    int o0 = d_off[n], deg = d_off[n + 1] - o0;
    float4 ad4 = *(const float4*)(d_ad1 + (size_t)n * 4);

    float m0 = -1e30f, m1 = -1e30f, m2 = -1e30f, m3 = -1e30f;
    float e0 = 0.f, e1 = 0.f, e2 = 0.f, e3 = 0.f;
    for (int i = lane; i < deg; i += 32) {
        int s = d_csr[o0 + i];
        float4 a = __ldg((const float4*)(d_as1 + (size_t)s * 4));
        online_upd(m0, e0, lrelu(a.x + ad4.x));
        online_upd(m1, e1, lrelu(a.y + ad4.y));
        online_upd(m2, e2, lrelu(a.z + ad4.z));
        online_upd(m3, e3, lrelu(a.w + ad4.w));
    }
#pragma unroll
    for (int s = 16; s; s >>= 1) {
        online_comb(m0, e0, __shfl_xor_sync(0xffffffffu, m0, s), __shfl_xor_sync(0xffffffffu, e0, s));
        online_comb(m1, e1, __shfl_xor_sync(0xffffffffu, m1, s), __shfl_xor_sync(0xffffffffu, e1, s));
        online_comb(m2, e2, __shfl_xor_sync(0xffffffffu, m2, s), __shfl_xor_sync(0xffffffffu, e2, s));
        online_comb(m3, e3, __shfl_xor_sync(0xffffffffu, m3, s), __shfl_xor_sync(0xffffffffu, e3, s));
    }
    float i0 = __fdividef(1.f, e0 + 1e-16f);
    float i1 = __fdividef(1.f, e1 + 1e-16f);
    float i2 = __fdividef(1.f, e2 + 1e-16f);
    float i3 = __fdividef(1.f, e3 + 1e-16f);

    int h = lane >> 3;
    float ih = (h < 2) ? (h == 0 ? i0 : i1) : (h == 2 ? i2 : i3);

    int sub = lane >> 2, hh = lane & 3;
    float adhh = (hh < 2) ? (hh == 0 ? ad4.x : ad4.y) : (hh == 2 ? ad4.z : ad4.w);
    float mhh  = (hh < 2) ? (hh == 0 ? m0 : m1) : (hh == 2 ? m2 : m3);

    float4 acc0 = make_float4(0.f, 0.f, 0.f, 0.f), acc1 = acc0;
    for (int j0 = 0; j0 < deg; j0 += 8) {
        int sld = (lane < 8 && j0 + lane < deg) ? d_csr[o0 + j0 + lane] : 0;
        int se = __shfl_sync(0xffffffffu, sld, sub);
        float a = __ldg(&d_as1[(size_t)se * 4 + hh]);
        float w_l = __expf(lrelu(a + adhh) - mhh);
        int lim = min(8, deg - j0);
        for (int j = 0; j < lim; j++) {
            int s = __shfl_sync(0xffffffffu, sld, j);
            float w = __shfl_sync(0xffffffffu, w_l, (j << 2) | h);
            const float4* hp = (const float4*)(d_h1 + (size_t)s * 256 + lane * 8);
            float4 v0 = __ldg(hp), v1 = __ldg(hp + 1);
            acc0.x = fmaf(w, v0.x, acc0.x); acc0.y = fmaf(w, v0.y, acc0.y);
            acc0.z = fmaf(w, v0.z, acc0.z); acc0.w = fmaf(w, v0.w, acc0.w);
            acc1.x = fmaf(w, v1.x, acc1.x); acc1.y = fmaf(w, v1.y, acc1.y);
            acc1.z = fmaf(w, v1.z, acc1.z); acc1.w = fmaf(w, v1.w, acc1.w);
        }
    }
    float4 b0 = *(const float4*)(bias + lane * 8);
    float4 b1 = *(const float4*)(bias + lane * 8 + 4);
    float o[8] = {acc0.x * ih + b0.x, acc0.y * ih + b0.y, acc0.z * ih + b0.z, acc0.w * ih + b0.w,
                  acc1.x * ih + b1.x, acc1.y * ih + b1.y, acc1.z * ih + b1.z, acc1.w * ih + b1.w};
#pragma unroll
    for (int i = 0; i < 8; i++) o[i] = o[i] > 0.f ? o[i] : expm1f(o[i]);
    float* gp = d_g1 + (size_t)n * 256 + lane * 8;
    *(float4*)gp       = make_float4(o[0], o[1], o[2], o[3]);
    *(float4*)(gp + 4) = make_float4(o[4], o[5], o[6], o[7]);
}

// ---------------- GAT layer 2: 128-thread blocks ----------------
__global__ void __launch_bounds__(128, 5) k_gat2(const float* __restrict__ bias) {
    int lane = threadIdx.x & 31, warp = threadIdx.x >> 5;
    int n = blockIdx.x * 4 + warp;
    if (n >= NN) return;
    int o0 = d_off[n], deg = d_off[n + 1] - o0;
    float ad = d_ad2[n];

    float m0 = -1e30f, e0 = 0.f;
    for (int i = lane; i < deg; i += 32) {
        int s = d_csr[o0 + i];
        online_upd(m0, e0, lrelu(__ldg(&d_as2[s]) + ad));
    }
#pragma unroll
    for (int s = 16; s; s >>= 1)
        online_comb(m0, e0, __shfl_xor_sync(0xffffffffu, m0, s), __shfl_xor_sync(0xffffffffu, e0, s));
    float inv = __fdividef(1.f, e0 + 1e-16f);

    float2 acc = make_float2(0.f, 0.f);
    for (int j0 = 0; j0 < deg; j0 += 32) {
        int sld = (j0 + lane < deg) ? d_csr[o0 + j0 + lane] : 0;
        float w_l = __expf(lrelu(__ldg(&d_as2[sld]) + ad) - m0);
        int lim = min(32, deg - j0);
        for (int j = 0; j < lim; j++) {
            int s = __shfl_sync(0xffffffffu, sld, j);
            float w = __shfl_sync(0xffffffffu, w_l, j);
            float2 v = __ldg((const float2*)(d_h2 + (size_t)s * 64 + lane * 2));
            acc.x = fmaf(w, v.x, acc.x);
            acc.y = fmaf(w, v.y, acc.y);
        }
    }
    float2 b = *(const float2*)(bias + lane * 2);
    *(float2*)(d_g2 + (size_t)n * 64 + lane * 2) =
        make_float2(acc.x * inv + b.x, acc.y * inv + b.y);
}

// ---------------- LSTM: node-pair f32x2, W in smem, smem-capped to 4 blocks/SM ----------------
// smem padded (sq cols 190) so 5 blocks exceed 228KB -> exactly 4 resident; regs stay
// <=102 via launch_bounds(128,5), leaving ~11.8K regs/SM for co-resident GAT blocks.
__global__ void __launch_bounds__(128, 5) k_lstm(const float* __restrict__ seq,
                                                 const float* __restrict__ Wih,
                                                 const float* __restrict__ Whh,
                                                 const float* __restrict__ bih,
                                                 const float* __restrict__ bhh) {
    __shared__ float4 wt[32][32];
    __shared__ float4 wxs[3][32];
    __shared__ float hb[4][32][8];
    __shared__ float xb[4][3][8];
    __shared__ float sq[32][190];   // padded: forces 4 blocks/SM

    int tid = threadIdx.x;
    int n0 = blockIdx.x * 32;

    for (int i = tid; i < 32 * 150; i += 128) {
        int node = i / 150, j = i - node * 150;
        int n = n0 + node;
        sq[node][j] = (n < NN) ? seq[(size_t)n * 150 + j] : 0.f;
    }

    for (int i = tid; i < 1024; i += 128) {
        int k = i >> 5, ln = i & 31;
        wt[k][ln] = make_float4(__ldg(&Whh[ln * 32 + k]),        __ldg(&Whh[(ln + 32) * 32 + k]),
                                __ldg(&Whh[(ln + 64) * 32 + k]), __ldg(&Whh[(ln + 96) * 32 + k]));
    }
    if (tid < 96) {
        int f = tid >> 5, ln = tid & 31;
        wxs[f][ln] = make_float4(Wih[ln * 3 + f],        Wih[(32 + ln) * 3 + f],
                                 Wih[(64 + ln) * 3 + f], Wih[(96 + ln) * 3 + f]);
    }

    int lane = tid & 31, warp = tid >> 5;

    unsigned long long b2[4];
#pragma unroll
    for (int g = 0; g < 4; g++) {
        float bv = bih[g * 32 + lane] + bhh[g * 32 + lane];
        b2[g] = pk2(bv, bv);
    }

    int nd3 = lane / 3, f3 = lane - nd3 * 3;
    bool xlane = (lane < 24);

    __syncthreads();

    float h[8], c[8];
#pragma unroll
    for (int j = 0; j < 8; j++) { h[j] = 0.f; c[j] = 0.f; }

#pragma unroll 1
    for (int t = 0; t < TT; t++) {
        if (xlane) xb[warp][f3][nd3] = sq[warp * 8 + nd3][t * 3 + f3];
        *(float4*)&hb[warp][lane][0] = make_float4(h[0], h[1], h[2], h[3]);
        *(float4*)&hb[warp][lane][4] = make_float4(h[4], h[5], h[6], h[7]);
        __syncwarp();

        unsigned long long zz[4][4];
#pragma unroll
        for (int g = 0; g < 4; g++)
#pragma unroll
            for (int p = 0; p < 4; p++) zz[g][p] = b2[g];

#pragma unroll
        for (int f = 0; f < 3; f++) {
            float4 wx = wxs[f][lane];
            unsigned long long wi2 = pk2(wx.x, wx.x);
            unsigned long long wf2 = pk2(wx.y, wx.y);
            unsigned long long wg2 = pk2(wx.z, wx.z);
            unsigned long long wo2 = pk2(wx.w, wx.w);
            ulonglong2 xA = *(const ulonglong2*)&xb[warp][f][0];
            ulonglong2 xB = *(const ulonglong2*)&xb[warp][f][4];
            zz[0][0] = fma2(xA.x, wi2, zz[0][0]); zz[0][1] = fma2(xA.y, wi2, zz[0][1]);
            zz[0][2] = fma2(xB.x, wi2, zz[0][2]); zz[0][3] = fma2(xB.y, wi2, zz[0][3]);
            zz[1][0] = fma2(xA.x, wf2, zz[1][0]); zz[1][1] = fma2(xA.y, wf2, zz[1][1]);
            zz[1][2] = fma2(xB.x, wf2, zz[1][2]); zz[1][3] = fma2(xB.y, wf2, zz[1][3]);
            zz[2][0] = fma2(xA.x, wg2, zz[2][0]); zz[2][1] = fma2(xA.y, wg2, zz[2][1]);
            zz[2][2] = fma2(xB.x, wg2, zz[2][2]); zz[2][3] = fma2(xB.y, wg2, zz[2][3]);
            zz[3][0] = fma2(xA.x, wo2, zz[3][0]); zz[3][1] = fma2(xA.y, wo2, zz[3][1]);
            zz[3][2] = fma2(xB.x, wo2, zz[3][2]); zz[3][3] = fma2(xB.y, wo2, zz[3][3]);
        }
#pragma unroll
        for (int k = 0; k < 32; k++) {
            float4 w4 = wt[k][lane];
            unsigned long long wi2 = pk2(w4.x, w4.x);
            unsigned long long wf2 = pk2(w4.y, w4.y);
            unsigned long long wg2 = pk2(w4.z, w4.z);
            unsigned long long wo2 = pk2(w4.w, w4.w);
            ulonglong2 hA = *(const ulonglong2*)&hb[warp][k][0];
            ulonglong2 hB = *(const ulonglong2*)&hb[warp][k][4];
            zz[0][0] = fma2(hA.x, wi2, zz[0][0]); zz[0][1] = fma2(hA.y, wi2, zz[0][1]);
            zz[0][2] = fma2(hB.x, wi2, zz[0][2]); zz[0][3] = fma2(hB.y, wi2, zz[0][3]);
            zz[1][0] = fma2(hA.x, wf2, zz[1][0]); zz[1][1] = fma2(hA.y, wf2, zz[1][1]);
            zz[1][2] = fma2(hB.x, wf2, zz[1][2]); zz[1][3] = fma2(hB.y, wf2, zz[1][3]);
            zz[2][0] = fma2(hA.x, wg2, zz[2][0]); zz[2][1] = fma2(hA.y, wg2, zz[2][1]);
            zz[2][2] = fma2(hB.x, wg2, zz[2][2]); zz[2][3] = fma2(hB.y, wg2, zz[2][3]);
            zz[3][0] = fma2(hA.x, wo2, zz[3][0]); zz[3][1] = fma2(hA.y, wo2, zz[3][1]);
            zz[3][2] = fma2(hB.x, wo2, zz[3][2]); zz[3][3] = fma2(hB.y, wo2, zz[3][3]);
        }
        __syncwarp();
#pragma unroll
        for (int p = 0; p < 4; p++) {
            float zi0, zi1, zf0, zf1, zg0, zg1, zo0, zo1;
            upk2(zz[0][p], zi0, zi1);
            upk2(zz[1][p], zf0, zf1);
            upk2(zz[2][p], zg0, zg1);
            upk2(zz[3][p], zo0, zo1);
            int j0 = 2 * p, j1 = 2 * p + 1;
            c[j0] = fsig(zf0) * c[j0] + fsig(zi0) * ftanh(zg0);
            h[j0] = fsig(zo0) * ftanh(c[j0]);
            c[j1] = fsig(zf1) * c[j1] + fsig(zi1) * ftanh(zg1);
            h[j1] = fsig(zo1) * ftanh(c[j1]);
        }
    }
#pragma unroll
    for (int j = 0; j < 8; j++) {
        int n = n0 + warp * 8 + j;
        if (n < NN) d_lstm[(size_t)n * 32 + lane] = h[j];
    }
}

// ---------------- fusion MLP: one warp per node ----------------
__global__ void __launch_bounds__(128) k_fuse(const float* __restrict__ Wf1,
                                              const float* __restrict__ bf1,
                                              const float* __restrict__ Wf2,
                                              const float* __restrict__ bf2,
                                              float* __restrict__ out) {
    __shared__ float w1s[96 * 64];
    __shared__ float w2s[128];
    __shared__ float b1s[64];
    int tid = threadIdx.x;
    for (int i = tid; i < 6144; i += 128) w1s[i] = Wf1[i];
    w2s[tid] = Wf2[tid];
    if (tid < 64) b1s[tid] = bf1[tid];
    __syncthreads();
    int lane = tid & 31, warp = tid >> 5;
    int n = blockIdx.x * 4 + warp;
    if (n >= NN) return;
    float f0 = d_g2[(size_t)n * 64 + lane];
    float f1 = d_g2[(size_t)n * 64 + 32 + lane];
    float f2 = d_lstm[(size_t)n * 32 + lane];
    float a0 = b1s[lane], a1 = b1s[32 + lane];
#pragma unroll
    for (int k = 0; k < 96; k++) {
        float srcv = (k < 32) ? f0 : ((k < 64) ? f1 : f2);
        float fk = __shfl_sync(0xffffffffu, srcv, k & 31);
        a0 = fmaf(fk, w1s[k * 64 + lane], a0);
        a1 = fmaf(fk, w1s[k * 64 + 32 + lane], a1);
    }
    a0 = fmaxf(a0, 0.f);
    a1 = fmaxf(a1, 0.f);
    float o0 = a0 * w2s[lane * 2 + 0] + a1 * w2s[(32 + lane) * 2 + 0];
    float o1 = a0 * w2s[lane * 2 + 1] + a1 * w2s[(32 + lane) * 2 + 1];
#pragma unroll
    for (int s = 16; s; s >>= 1) {
        o0 += __shfl_xor_sync(0xffffffffu, o0, s);
        o1 += __shfl_xor_sync(0xffffffffu, o1, s);
    }
    if (lane == 0) {
        out[(size_t)n * 2 + 0] = o0 + bf2[0];
        out[(size_t)n * 2 + 1] = o1 + bf2[1];
    }
}

// ---------------- launch ----------------
extern "C" void kernel_launch(void* const* d_in, const int* in_sizes, int n_in,
                              void* d_out, int out_size) {
    const float* x    = (const float*)d_in[0];
    const int*   ei   = (const int*)d_in[1];
    const float* seq  = (const float*)d_in[2];
    const float* W1   = (const float*)d_in[3];
    const float* as1  = (const float*)d_in[4];
    const float* ad1  = (const float*)d_in[5];
    const float* b1   = (const float*)d_in[6];
    const float* W2   = (const float*)d_in[7];
    const float* as2  = (const float*)d_in[8];
    const float* ad2  = (const float*)d_in[9];
    const float* b2   = (const float*)d_in[10];
    const float* Wih  = (const float*)d_in[11];
    const float* Whh  = (const float*)d_in[12];
    const float* bih  = (const float*)d_in[13];
    const float* bhh  = (const float*)d_in[14];
    const float* Wf1  = (const float*)d_in[15];
    const float* bf1  = (const float*)d_in[16];
    const float* Wf2  = (const float*)d_in[17];
    const float* bf2  = (const float*)d_in[18];
    float* out = (float*)d_out;

    float *h1p, *g1p, *h2p, *as1p, *ad1p, *as2p, *ad2p;
    cudaGetSymbolAddress((void**)&h1p, d_h1);
    cudaGetSymbolAddress((void**)&g1p, d_g1);
    cudaGetSymbolAddress((void**)&h2p, d_h2);
    cudaGetSymbolAddress((void**)&as1p, d_as1);
    cudaGetSymbolAddress((void**)&ad1p, d_ad1);
    cudaGetSymbolAddress((void**)&as2p, d_as2);
    cudaGetSymbolAddress((void**)&ad2p, d_ad2);

    static cudaStream_t s_a = 0, s_c = 0, s_m = 0;
    static cudaEvent_t e_fork = 0, e_a = 0, e_c = 0, e_m = 0;
    if (!s_a) {
        int pLow, pHigh;
        cudaDeviceGetStreamPriorityRange(&pLow, &pHigh);
        cudaStreamCreateWithPriority(&s_a, cudaStreamNonBlocking, pHigh);
        cudaStreamCreateWithPriority(&s_m, cudaStreamNonBlocking, pHigh);
        cudaStreamCreateWithPriority(&s_c, cudaStreamNonBlocking, pLow);
        cudaEventCreateWithFlags(&e_fork, cudaEventDisableTiming);
        cudaEventCreateWithFlags(&e_a, cudaEventDisableTiming);
        cudaEventCreateWithFlags(&e_c, cudaEventDisableTiming);
        cudaEventCreateWithFlags(&e_m, cudaEventDisableTiming);
    }

    cudaEventRecord(e_fork, 0);
    cudaStreamWaitEvent(s_a, e_fork, 0);
    cudaStreamWaitEvent(s_c, e_fork, 0);
    cudaStreamWaitEvent(s_m, e_fork, 0);

    // CSR build; sgemm1 4th launch -> profiled slot (control)
    k_zero_deg<<<(NN + 256) / 256, 256, 0, s_a>>>();                            // 1
    k_hist<<<(ETOT + 255) / 256, 256, 0, s_a>>>(ei);                            // 2
    k_scan1<<<NB, 1024, 0, s_a>>>();                                            // 3
    k_sgemm<128, 1><<<dim3(4, (NN + 127) / 128), 256, 0, s_m>>>(x, W1, h1p, NN, 256,
                                                                as1, ad1, as1p, ad1p); // 4
    k_scan2<<<1, 64, 0, s_a>>>();                                               // 5
    k_scan3<<<(NN + 255) / 256, 256, 0, s_a>>>();                               // 6
    k_scatter<<<(ETOT + 255) / 256, 256, 0, s_a>>>(ei);                         // 7
    cudaEventRecord(e_a, s_a);

    // low-priority LSTM (4 blocks/SM -> spare regs for co-resident GAT blocks)
    k_lstm<<<(NN + 31) / 32, 128, 0, s_c>>>(seq, Wih, Whh, bih, bhh);
    cudaEventRecord(e_c, s_c);

    // high-priority GAT chain: 128-thread blocks co-reside with LSTM
    cudaStreamWaitEvent(s_m, e_a, 0);
    k_gat1<<<(NN + 3) / 4, 128, 0, s_m>>>(b1);
    k_sgemm<256, 2><<<dim3(1, (NN + 127) / 128), 256, 0, s_m>>>(g1p, W2, h2p, NN, 64,
                                                                as2, ad2, as2p, ad2p);
    k_gat2<<<(NN + 3) / 4, 128, 0, s_m>>>(b2);
    cudaStreamWaitEvent(s_m, e_c, 0);
    k_fuse<<<(NN + 3) / 4, 128, 0, s_m>>>(Wf1, bf1, Wf2, bf2, out);
    cudaEventRecord(e_m, s_m);
    cudaStreamWaitEvent(0, e_m, 0);
}